// round 1
// baseline (speedup 1.0000x reference)
#include <cuda_runtime.h>
#include <math.h>

#define B_    16
#define S_    577
#define D_    1280
#define H_    16
#define HD_   80
#define HALF_ 40
#define M_    (B_*S_)   // 9232

// Scratch (allocation-free rule: __device__ globals)
__device__ __align__(16) float g_q[B_*H_*S_*HD_];
__device__ __align__(16) float g_k[B_*H_*S_*HD_];
__device__ __align__(16) float g_v[B_*H_*S_*HD_];
__device__ __align__(16) float g_attn[B_*S_*D_];

// ---------------------------------------------------------------------------
// GEMM: C[m,n] = sum_k A[m,k] * Bw[n,k] + bias[n]
// A: [M,K] row-major, Bw: [N,K] row-major (i.e. C = A * Bw^T + bias)
// scatter_qkv=1: write to (B,H,S,HD) layout; else row-major [M,N].
// ---------------------------------------------------------------------------
#define BM 128
#define BN 128
#define BK 16

__global__ __launch_bounds__(256)
void gemm_kernel(const float* __restrict__ A, const float* __restrict__ Bw,
                 const float* __restrict__ bias, float* __restrict__ C,
                 int M, int N, int K, int scatter_qkv)
{
    __shared__ __align__(16) float As[BK][BM + 4];
    __shared__ __align__(16) float Bs[BK][BN + 4];

    const int tid = threadIdx.x;
    const int bm = blockIdx.y, bn = blockIdx.x;
    const int tr = tid >> 4, tc = tid & 15;

    float acc[8][8];
#pragma unroll
    for (int i = 0; i < 8; i++)
#pragma unroll
        for (int j = 0; j < 8; j++) acc[i][j] = 0.f;

    for (int k0 = 0; k0 < K; k0 += BK) {
        // Load A tile: 128x16 floats = 512 float4, 2 per thread
#pragma unroll
        for (int it = 0; it < 2; it++) {
            int v = tid + it * 256;
            int r = v >> 2, c4 = (v & 3) * 4;
            int m = bm * BM + r;
            float4 f = (m < M) ? *(const float4*)(A + (size_t)m * K + k0 + c4)
                               : make_float4(0.f, 0.f, 0.f, 0.f);
            As[c4 + 0][r] = f.x; As[c4 + 1][r] = f.y;
            As[c4 + 2][r] = f.z; As[c4 + 3][r] = f.w;
        }
        // Load B tile
#pragma unroll
        for (int it = 0; it < 2; it++) {
            int v = tid + it * 256;
            int r = v >> 2, c4 = (v & 3) * 4;
            int n = bn * BN + r;
            float4 f = (n < N) ? *(const float4*)(Bw + (size_t)n * K + k0 + c4)
                               : make_float4(0.f, 0.f, 0.f, 0.f);
            Bs[c4 + 0][r] = f.x; Bs[c4 + 1][r] = f.y;
            Bs[c4 + 2][r] = f.z; Bs[c4 + 3][r] = f.w;
        }
        __syncthreads();

#pragma unroll
        for (int kk = 0; kk < BK; kk++) {
            float a[8], b[8];
            *(float4*)&a[0] = *(const float4*)&As[kk][tr * 8];
            *(float4*)&a[4] = *(const float4*)&As[kk][tr * 8 + 4];
            *(float4*)&b[0] = *(const float4*)&Bs[kk][tc * 8];
            *(float4*)&b[4] = *(const float4*)&Bs[kk][tc * 8 + 4];
#pragma unroll
            for (int i = 0; i < 8; i++)
#pragma unroll
                for (int j = 0; j < 8; j++)
                    acc[i][j] = fmaf(a[i], b[j], acc[i][j]);
        }
        __syncthreads();
    }

    const int m0 = bm * BM + tr * 8;
    const int n0 = bn * BN + tc * 8;
#pragma unroll
    for (int i = 0; i < 8; i++) {
        int m = m0 + i;
        if (m >= M) continue;
#pragma unroll
        for (int j = 0; j < 8; j++) {
            int n = n0 + j;
            float val = acc[i][j] + bias[n];
            if (scatter_qkv) {
                int b = m / S_, s = m - b * S_;
                int h = n / HD_, d = n - h * HD_;
                C[((size_t)(b * H_ + h) * S_ + s) * HD_ + d] = val;
            } else {
                C[(size_t)m * N + n] = val;
            }
        }
    }
}

// ---------------------------------------------------------------------------
// RoPE (interleaved pairs) applied in-place to q and k in (B,H,S,HD) layout.
// ---------------------------------------------------------------------------
__global__ __launch_bounds__(256)
void rope_kernel(float* __restrict__ q, float* __restrict__ k,
                 const float* __restrict__ fc, const float* __restrict__ fs)
{
    int idx = blockIdx.x * blockDim.x + threadIdx.x;
    const int total = B_ * H_ * S_ * HALF_;
    if (idx >= total) return;
    int j = idx % HALF_;
    int s = (idx / HALF_) % S_;
    int bh = idx / (HALF_ * S_);
    float c  = fc[s * HALF_ + j];
    float sn = fs[s * HALF_ + j];
    size_t base = ((size_t)bh * S_ + s) * HD_ + 2 * j;

    float xr = q[base], xi = q[base + 1];
    q[base]     = xr * c - xi * sn;
    q[base + 1] = xr * sn + xi * c;
    xr = k[base]; xi = k[base + 1];
    k[base]     = xr * c - xi * sn;
    k[base + 1] = xr * sn + xi * c;
}

// ---------------------------------------------------------------------------
// Flash attention: per (b,h,q-tile of 64) block, online softmax over key tiles.
// ---------------------------------------------------------------------------
#define BQ  64
#define BKT 64
#define QS  84   // padded row stride for q/k/v tiles (16B-aligned float4 rows)
#define PS  68   // padded row stride for probs tile

__global__ __launch_bounds__(256)
void attn_kernel(const float* __restrict__ q, const float* __restrict__ k,
                 const float* __restrict__ v, float* __restrict__ out)
{
    extern __shared__ __align__(16) float sm[];
    float* q_s  = sm;                     // BQ*QS
    float* k_s  = q_s + BQ * QS;          // BKT*QS
    float* v_s  = k_s + BKT * QS;         // BKT*QS
    float* p_s  = v_s + BKT * QS;         // BQ*PS
    float* m_s  = p_s + BQ * PS;          // BQ
    float* l_s  = m_s + BQ;               // BQ
    float* al_s = l_s + BQ;               // BQ
    float* red  = al_s + BQ;              // BQ*4

    const int tid = threadIdx.x;
    const int qt = blockIdx.x, h = blockIdx.y, b = blockIdx.z;
    const int bh = b * H_ + h;
    const float* qp = q + (size_t)bh * S_ * HD_;
    const float* kp = k + (size_t)bh * S_ * HD_;
    const float* vp = v + (size_t)bh * S_ * HD_;
    const int q0 = qt * BQ;

    // Load Q tile
    for (int idx = tid; idx < BQ * HD_; idx += 256) {
        int r = idx / HD_, d = idx - r * HD_;
        int srow = q0 + r;
        q_s[r * QS + d] = (srow < S_) ? qp[(size_t)srow * HD_ + d] : 0.f;
    }
    if (tid < BQ) { m_s[tid] = -1e30f; l_s[tid] = 0.f; }

    const int tr = tid >> 4, tc = tid & 15;
    float o[4][5];
#pragma unroll
    for (int i = 0; i < 4; i++)
#pragma unroll
        for (int dd = 0; dd < 5; dd++) o[i][dd] = 0.f;

    const float rscale = 0.11180339887498949f;  // 1/sqrt(80)
    const int ntiles = (S_ + BKT - 1) / BKT;    // 10

    for (int kt = 0; kt < ntiles; kt++) {
        __syncthreads();  // previous PV reads done before reloading k_s/v_s
        for (int idx = tid; idx < BKT * HD_; idx += 256) {
            int r = idx / HD_, d = idx - r * HD_;
            int srow = kt * BKT + r;
            if (srow < S_) {
                k_s[r * QS + d] = kp[(size_t)srow * HD_ + d];
                v_s[r * QS + d] = vp[(size_t)srow * HD_ + d];
            } else {
                k_s[r * QS + d] = 0.f;
                v_s[r * QS + d] = 0.f;
            }
        }
        __syncthreads();

        // scores: 4x4 micro-tile per thread
        float acc[4][4];
#pragma unroll
        for (int i = 0; i < 4; i++)
#pragma unroll
            for (int j = 0; j < 4; j++) acc[i][j] = 0.f;

#pragma unroll
        for (int d0 = 0; d0 < HD_; d0 += 4) {
            float4 qa[4], kb[4];
#pragma unroll
            for (int i = 0; i < 4; i++)
                qa[i] = *(const float4*)&q_s[(tr * 4 + i) * QS + d0];
#pragma unroll
            for (int j = 0; j < 4; j++)
                kb[j] = *(const float4*)&k_s[(tc * 4 + j) * QS + d0];
#pragma unroll
            for (int i = 0; i < 4; i++)
#pragma unroll
                for (int j = 0; j < 4; j++)
                    acc[i][j] += qa[i].x * kb[j].x + qa[i].y * kb[j].y
                               + qa[i].z * kb[j].z + qa[i].w * kb[j].w;
        }
#pragma unroll
        for (int i = 0; i < 4; i++)
#pragma unroll
            for (int j = 0; j < 4; j++) {
                int col = tc * 4 + j;
                float lv = (kt * BKT + col < S_) ? acc[i][j] * rscale : -1e30f;
                p_s[(tr * 4 + i) * PS + col] = lv;
            }
        __syncthreads();

        // online softmax: 4 threads per row
        {
            int row = tid >> 2, part = tid & 3;
            float mloc = -1e30f;
            for (int c = part * 16; c < part * 16 + 16; c++)
                mloc = fmaxf(mloc, p_s[row * PS + c]);
            red[row * 4 + part] = mloc;
        }
        __syncthreads();
        if (tid < BQ) {
            float mn = fmaxf(fmaxf(red[tid * 4], red[tid * 4 + 1]),
                             fmaxf(red[tid * 4 + 2], red[tid * 4 + 3]));
            mn = fmaxf(mn, m_s[tid]);
            al_s[tid] = __expf(m_s[tid] - mn);
            m_s[tid] = mn;
        }
        __syncthreads();
        {
            int row = tid >> 2, part = tid & 3;
            float mrow = m_s[row];
            float ssum = 0.f;
            for (int c = part * 16; c < part * 16 + 16; c++) {
                float e = __expf(p_s[row * PS + c] - mrow);
                p_s[row * PS + c] = e;
                ssum += e;
            }
            red[row * 4 + part] = ssum;
        }
        __syncthreads();
        if (tid < BQ) {
            l_s[tid] = l_s[tid] * al_s[tid]
                     + red[tid * 4] + red[tid * 4 + 1]
                     + red[tid * 4 + 2] + red[tid * 4 + 3];
        }
        __syncthreads();

        // PV: rows tr*4+i (same as QK), dims tc*5+dd
        float alpha[4];
#pragma unroll
        for (int i = 0; i < 4; i++) alpha[i] = al_s[tr * 4 + i];
#pragma unroll
        for (int i = 0; i < 4; i++)
#pragma unroll
            for (int dd = 0; dd < 5; dd++) o[i][dd] *= alpha[i];

        for (int c = 0; c < BKT; c++) {
            float pv[4];
#pragma unroll
            for (int i = 0; i < 4; i++) pv[i] = p_s[(tr * 4 + i) * PS + c];
#pragma unroll
            for (int dd = 0; dd < 5; dd++) {
                float vv = v_s[c * QS + tc * 5 + dd];
#pragma unroll
                for (int i = 0; i < 4; i++) o[i][dd] = fmaf(pv[i], vv, o[i][dd]);
            }
        }
    }

    // write out in (B,S,D) layout
#pragma unroll
    for (int i = 0; i < 4; i++) {
        int srow = q0 + tr * 4 + i;
        if (srow >= S_) continue;
        float inv = 1.f / l_s[tr * 4 + i];
#pragma unroll
        for (int dd = 0; dd < 5; dd++)
            out[((size_t)b * S_ + srow) * D_ + h * HD_ + tc * 5 + dd] = o[i][dd] * inv;
    }
}

// ---------------------------------------------------------------------------
extern "C" void kernel_launch(void* const* d_in, const int* in_sizes, int n_in,
                              void* d_out, int out_size)
{
    const float* hs = (const float*)d_in[0];
    const float* fc = (const float*)d_in[1];
    const float* fs = (const float*)d_in[2];
    const float* Wq = (const float*)d_in[3];
    const float* bq = (const float*)d_in[4];
    const float* Wk = (const float*)d_in[5];
    const float* bk = (const float*)d_in[6];
    const float* Wv = (const float*)d_in[7];
    const float* bv = (const float*)d_in[8];
    const float* Wo = (const float*)d_in[9];
    const float* bo = (const float*)d_in[10];
    float* out = (float*)d_out;

    float *pq, *pk, *pv, *pa;
    cudaGetSymbolAddress((void**)&pq, g_q);
    cudaGetSymbolAddress((void**)&pk, g_k);
    cudaGetSymbolAddress((void**)&pv, g_v);
    cudaGetSymbolAddress((void**)&pa, g_attn);

    dim3 ggrid(D_ / BN, (M_ + BM - 1) / BM);  // (10, 73)

    gemm_kernel<<<ggrid, 256>>>(hs, Wq, bq, pq, M_, D_, D_, 1);
    gemm_kernel<<<ggrid, 256>>>(hs, Wk, bk, pk, M_, D_, D_, 1);
    gemm_kernel<<<ggrid, 256>>>(hs, Wv, bv, pv, M_, D_, D_, 1);

    int pairs = B_ * H_ * S_ * HALF_;
    rope_kernel<<<(pairs + 255) / 256, 256>>>(pq, pk, fc, fs);

    size_t smem = (size_t)(BQ * QS + 2 * BKT * QS + BQ * PS + BQ * 7) * sizeof(float);
    cudaFuncSetAttribute(attn_kernel, cudaFuncAttributeMaxDynamicSharedMemorySize,
                         (int)smem);
    attn_kernel<<<dim3((S_ + BQ - 1) / BQ, H_, B_), 256, smem>>>(pq, pk, pv, pa);

    gemm_kernel<<<ggrid, 256>>>(pa, Wo, bo, out, M_, D_, D_, 0);
}

// round 3
// speedup vs baseline: 1.7251x; 1.7251x over previous
#include <cuda_runtime.h>
#include <cuda_bf16.h>
#include <math.h>
#include <stdint.h>

#define B_    16
#define S_    577
#define D_    1280
#define H_    16
#define HD_   80
#define HALF_ 40
#define M_    (B_*S_)   // 9232
#define K_    1280
#define N_    1280

// ---------------------------------------------------------------- scratch
__device__ __align__(16) float g_q[B_*H_*S_*HD_];
__device__ __align__(16) float g_k[B_*H_*S_*HD_];
__device__ __align__(16) float g_v[B_*H_*S_*HD_];
__device__ __align__(16) __nv_bfloat16 g_hs_hi[M_*K_];
__device__ __align__(16) __nv_bfloat16 g_hs_lo[M_*K_];
__device__ __align__(16) __nv_bfloat16 g_w_hi[4*K_*N_];
__device__ __align__(16) __nv_bfloat16 g_w_lo[4*K_*N_];
__device__ __align__(16) __nv_bfloat16 g_at_hi[M_*K_];
__device__ __align__(16) __nv_bfloat16 g_at_lo[M_*K_];

// ---------------------------------------------------------------- helpers
__device__ __forceinline__ uint32_t smem_u32(const void* p) {
    uint32_t a;
    asm("{ .reg .u64 t; cvta.to.shared.u64 t, %1; cvt.u32.u64 %0, t; }"
        : "=r"(a) : "l"(p));
    return a;
}

__device__ __forceinline__ void cp16(uint32_t dst, const void* src, int sz) {
    asm volatile("cp.async.cg.shared.global [%0], [%1], 16, %2;"
                 :: "r"(dst), "l"(src), "r"(sz) : "memory");
}
#define CP_COMMIT() asm volatile("cp.async.commit_group;" ::: "memory")

__device__ __forceinline__ void ldx4(uint32_t* r, uint32_t addr) {
    asm volatile("ldmatrix.sync.aligned.m8n8.x4.shared.b16 {%0,%1,%2,%3}, [%4];"
                 : "=r"(r[0]), "=r"(r[1]), "=r"(r[2]), "=r"(r[3]) : "r"(addr));
}

__device__ __forceinline__ void hmma(float* d, const uint32_t* a, const uint32_t* b) {
    asm volatile(
        "mma.sync.aligned.m16n8k16.row.col.f32.bf16.bf16.f32 "
        "{%0,%1,%2,%3}, {%4,%5,%6,%7}, {%8,%9}, {%0,%1,%2,%3};"
        : "+f"(d[0]), "+f"(d[1]), "+f"(d[2]), "+f"(d[3])
        : "r"(a[0]), "r"(a[1]), "r"(a[2]), "r"(a[3]), "r"(b[0]), "r"(b[1]));
}

// ---------------------------------------------------------------- fp32 -> bf16 hi/lo split
__global__ __launch_bounds__(256)
void split_kernel(const float* __restrict__ x,
                  __nv_bfloat16* __restrict__ hi,
                  __nv_bfloat16* __restrict__ lo, int n)
{
    int i = blockIdx.x * blockDim.x + threadIdx.x;
    if (i >= n) return;
    float v = x[i];
    __nv_bfloat16 h = __float2bfloat16(v);
    hi[i] = h;
    lo[i] = __float2bfloat16(v - __bfloat162float(h));
}

// ---------------------------------------------------------------- HMMA GEMM
// C[m,n] = sum_k (Ahi+Alo)[m,k]*(Bhi+Blo)[n,k] + bias[n]  (lo*lo dropped)
// CTA tile 128x128, BK=32 bf16, double-buffered cp.async stages.
// 8 warps as 2(M) x 4(N); warp tile 64x32; mma m16n8k16 micro-tiles 4x4.
#define SPADB 80                    // bytes per smem row (32 bf16 + 8 pad)
#define TILEB (128*SPADB)           // 10240 bytes per 128x32 tile
#define STAGEB (4*TILEB)            // Ahi,Alo,Bhi,Blo
#define GEMM_SMEM (2*STAGEB)        // 81920
#define NIT (K_/32)                 // 40

__global__ __launch_bounds__(256)
void gemm_hmma(const __nv_bfloat16* __restrict__ Ahi, const __nv_bfloat16* __restrict__ Alo,
               const __nv_bfloat16* __restrict__ Bhi, const __nv_bfloat16* __restrict__ Blo,
               const float* __restrict__ bias, float* __restrict__ C,
               int M, int scatter)
{
    extern __shared__ __align__(16) char smem[];
    const int tid = threadIdx.x, wid = tid >> 5, lane = tid & 31;
    const int bn = blockIdx.x, bm = blockIdx.y;
    const int wm = wid >> 2, wn = wid & 3;
    const int row0A = bm * 128, row0B = bn * 128;
    const uint32_t sbase = smem_u32(smem);

    float acc[4][4][4];
#pragma unroll
    for (int i = 0; i < 4; i++)
#pragma unroll
        for (int j = 0; j < 4; j++)
#pragma unroll
            for (int c = 0; c < 4; c++) acc[i][j][c] = 0.f;

    // ---- stage loader (cp.async) ----
    auto load_stage = [&](int st, int k0) {
        uint32_t sdst = sbase + st * STAGEB;
#pragma unroll
        for (int t = 0; t < 8; t++) {
            int idx = tid + t * 256;
            int tile = idx >> 9;          // 0..3
            int r = (idx >> 2) & 127;
            int seg = idx & 3;
            uint32_t d = sdst + tile * TILEB + r * SPADB + seg * 16;
            const __nv_bfloat16* sp;
            int sz = 16;
            if (tile < 2) {
                int row = row0A + r;
                if (row >= M) { row = M - 1; sz = 0; }
                sp = (tile == 0 ? Ahi : Alo) + (size_t)row * K_ + k0 + seg * 8;
            } else {
                int row = row0B + r;
                sp = (tile == 2 ? Bhi : Blo) + (size_t)row * K_ + k0 + seg * 8;
            }
            cp16(d, sp, sz);
        }
        CP_COMMIT();
    };

    // per-thread ldmatrix base offsets
    const uint32_t a_lane = (uint32_t)((wm * 64 + (lane & 15)) * SPADB + (lane >> 4) * 16);
    const uint32_t b_lane = (uint32_t)((wn * 32 + ((lane >> 4) << 3) + (lane & 7)) * SPADB
                                       + ((lane >> 3) & 1) * 16);

    load_stage(0, 0);

    for (int it = 0; it < NIT; it++) {
        int cur = it & 1;
        if (it + 1 < NIT) {
            load_stage(cur ^ 1, (it + 1) * 32);
            asm volatile("cp.async.wait_group 1;" ::: "memory");
        } else {
            asm volatile("cp.async.wait_group 0;" ::: "memory");
        }
        __syncthreads();

        uint32_t scur = sbase + cur * STAGEB;
#pragma unroll
        for (int kk = 0; kk < 2; kk++) {
            uint32_t ab = scur + a_lane + kk * 32;
            uint32_t bb = scur + 2 * TILEB + b_lane + kk * 32;

            uint32_t ah[4][4], al[4][4], bh[4][2], bl[4][2];
#pragma unroll
            for (int mi = 0; mi < 4; mi++) ldx4(ah[mi], ab + mi * 16 * SPADB);
#pragma unroll
            for (int mi = 0; mi < 4; mi++) ldx4(al[mi], ab + TILEB + mi * 16 * SPADB);
#pragma unroll
            for (int np = 0; np < 2; np++) {
                uint32_t r[4];
                ldx4(r, bb + np * 16 * SPADB);
                bh[np * 2][0] = r[0]; bh[np * 2][1] = r[1];
                bh[np * 2 + 1][0] = r[2]; bh[np * 2 + 1][1] = r[3];
                ldx4(r, bb + TILEB + np * 16 * SPADB);
                bl[np * 2][0] = r[0]; bl[np * 2][1] = r[1];
                bl[np * 2 + 1][0] = r[2]; bl[np * 2 + 1][1] = r[3];
            }
#pragma unroll
            for (int mi = 0; mi < 4; mi++)
#pragma unroll
                for (int ni = 0; ni < 4; ni++) hmma(acc[mi][ni], ah[mi], bh[ni]);
#pragma unroll
            for (int mi = 0; mi < 4; mi++)
#pragma unroll
                for (int ni = 0; ni < 4; ni++) hmma(acc[mi][ni], ah[mi], bl[ni]);
#pragma unroll
            for (int mi = 0; mi < 4; mi++)
#pragma unroll
                for (int ni = 0; ni < 4; ni++) hmma(acc[mi][ni], al[mi], bh[ni]);
        }
        __syncthreads();
    }

    // ---- epilogue ----
    const int mrow = (lane >> 2);
    const int ncol = (lane & 3) * 2;
#pragma unroll
    for (int mi = 0; mi < 4; mi++) {
#pragma unroll
        for (int h2 = 0; h2 < 2; h2++) {
            int m = row0A + wm * 64 + mi * 16 + mrow + h2 * 8;
            if (m >= M) continue;
            int bb2 = m / S_, ss = m - bb2 * S_;
#pragma unroll
            for (int ni = 0; ni < 4; ni++) {
                int n0 = bn * 128 + wn * 32 + ni * 8 + ncol;
                float2 v;
                v.x = acc[mi][ni][h2 * 2] + bias[n0];
                v.y = acc[mi][ni][h2 * 2 + 1] + bias[n0 + 1];
                if (scatter) {
                    int h = n0 / HD_, d = n0 - h * HD_;
                    *(float2*)&((float*)C)[((size_t)(bb2 * H_ + h) * S_ + ss) * HD_ + d] = v;
                } else {
                    *(float2*)&C[(size_t)m * N_ + n0] = v;
                }
            }
        }
    }
}

// ---------------------------------------------------------------- RoPE
__global__ __launch_bounds__(256)
void rope_kernel(float* __restrict__ q, float* __restrict__ k,
                 const float* __restrict__ fc, const float* __restrict__ fs)
{
    int idx = blockIdx.x * blockDim.x + threadIdx.x;
    const int total = B_ * H_ * S_ * HALF_;
    if (idx >= total) return;
    int j = idx % HALF_;
    int s = (idx / HALF_) % S_;
    int bh = idx / (HALF_ * S_);
    float c  = fc[s * HALF_ + j];
    float sn = fs[s * HALF_ + j];
    size_t base = ((size_t)bh * S_ + s) * HD_ + 2 * j;

    float xr = q[base], xi = q[base + 1];
    q[base]     = xr * c - xi * sn;
    q[base + 1] = xr * sn + xi * c;
    xr = k[base]; xi = k[base + 1];
    k[base]     = xr * c - xi * sn;
    k[base + 1] = xr * sn + xi * c;
}

// ---------------------------------------------------------------- flash attention (fp32 SIMT)
#define BQ  64
#define BKT 64
#define QS  84
#define PS  68

__global__ __launch_bounds__(256)
void attn_kernel(const float* __restrict__ q, const float* __restrict__ k,
                 const float* __restrict__ v,
                 __nv_bfloat16* __restrict__ out_hi,
                 __nv_bfloat16* __restrict__ out_lo)
{
    extern __shared__ __align__(16) float sm[];
    float* q_s  = sm;
    float* k_s  = q_s + BQ * QS;
    float* v_s  = k_s + BKT * QS;
    float* p_s  = v_s + BKT * QS;
    float* m_s  = p_s + BQ * PS;
    float* l_s  = m_s + BQ;
    float* al_s = l_s + BQ;
    float* red  = al_s + BQ;

    const int tid = threadIdx.x;
    const int qt = blockIdx.x, h = blockIdx.y, b = blockIdx.z;
    const int bh = b * H_ + h;
    const float* qp = q + (size_t)bh * S_ * HD_;
    const float* kp = k + (size_t)bh * S_ * HD_;
    const float* vp = v + (size_t)bh * S_ * HD_;
    const int q0 = qt * BQ;

    for (int idx = tid; idx < BQ * HD_; idx += 256) {
        int r = idx / HD_, d = idx - r * HD_;
        int srow = q0 + r;
        q_s[r * QS + d] = (srow < S_) ? qp[(size_t)srow * HD_ + d] : 0.f;
    }
    if (tid < BQ) { m_s[tid] = -1e30f; l_s[tid] = 0.f; }

    const int tr = tid >> 4, tc = tid & 15;
    float o[4][5];
#pragma unroll
    for (int i = 0; i < 4; i++)
#pragma unroll
        for (int dd = 0; dd < 5; dd++) o[i][dd] = 0.f;

    const float rscale = 0.11180339887498949f;
    const int ntiles = (S_ + BKT - 1) / BKT;

    for (int kt = 0; kt < ntiles; kt++) {
        __syncthreads();
        for (int idx = tid; idx < BKT * HD_; idx += 256) {
            int r = idx / HD_, d = idx - r * HD_;
            int srow = kt * BKT + r;
            if (srow < S_) {
                k_s[r * QS + d] = kp[(size_t)srow * HD_ + d];
                v_s[r * QS + d] = vp[(size_t)srow * HD_ + d];
            } else {
                k_s[r * QS + d] = 0.f;
                v_s[r * QS + d] = 0.f;
            }
        }
        __syncthreads();

        float acc[4][4];
#pragma unroll
        for (int i = 0; i < 4; i++)
#pragma unroll
            for (int j = 0; j < 4; j++) acc[i][j] = 0.f;

#pragma unroll
        for (int d0 = 0; d0 < HD_; d0 += 4) {
            float4 qa[4], kb[4];
#pragma unroll
            for (int i = 0; i < 4; i++)
                qa[i] = *(const float4*)&q_s[(tr * 4 + i) * QS + d0];
#pragma unroll
            for (int j = 0; j < 4; j++)
                kb[j] = *(const float4*)&k_s[(tc * 4 + j) * QS + d0];
#pragma unroll
            for (int i = 0; i < 4; i++)
#pragma unroll
                for (int j = 0; j < 4; j++)
                    acc[i][j] += qa[i].x * kb[j].x + qa[i].y * kb[j].y
                               + qa[i].z * kb[j].z + qa[i].w * kb[j].w;
        }
#pragma unroll
        for (int i = 0; i < 4; i++)
#pragma unroll
            for (int j = 0; j < 4; j++) {
                int col = tc * 4 + j;
                float lv = (kt * BKT + col < S_) ? acc[i][j] * rscale : -1e30f;
                p_s[(tr * 4 + i) * PS + col] = lv;
            }
        __syncthreads();

        {
            int row = tid >> 2, part = tid & 3;
            float mloc = -1e30f;
            for (int c = part * 16; c < part * 16 + 16; c++)
                mloc = fmaxf(mloc, p_s[row * PS + c]);
            red[row * 4 + part] = mloc;
        }
        __syncthreads();
        if (tid < BQ) {
            float mn = fmaxf(fmaxf(red[tid * 4], red[tid * 4 + 1]),
                             fmaxf(red[tid * 4 + 2], red[tid * 4 + 3]));
            mn = fmaxf(mn, m_s[tid]);
            al_s[tid] = __expf(m_s[tid] - mn);
            m_s[tid] = mn;
        }
        __syncthreads();
        {
            int row = tid >> 2, part = tid & 3;
            float mrow = m_s[row];
            float ssum = 0.f;
            for (int c = part * 16; c < part * 16 + 16; c++) {
                float e = __expf(p_s[row * PS + c] - mrow);
                p_s[row * PS + c] = e;
                ssum += e;
            }
            red[row * 4 + part] = ssum;
        }
        __syncthreads();
        if (tid < BQ) {
            l_s[tid] = l_s[tid] * al_s[tid]
                     + red[tid * 4] + red[tid * 4 + 1]
                     + red[tid * 4 + 2] + red[tid * 4 + 3];
        }
        __syncthreads();

        float alpha[4];
#pragma unroll
        for (int i = 0; i < 4; i++) alpha[i] = al_s[tr * 4 + i];
#pragma unroll
        for (int i = 0; i < 4; i++)
#pragma unroll
            for (int dd = 0; dd < 5; dd++) o[i][dd] *= alpha[i];

        for (int c = 0; c < BKT; c++) {
            float pv[4];
#pragma unroll
            for (int i = 0; i < 4; i++) pv[i] = p_s[(tr * 4 + i) * PS + c];
#pragma unroll
            for (int dd = 0; dd < 5; dd++) {
                float vv = v_s[c * QS + tc * 5 + dd];
#pragma unroll
                for (int i = 0; i < 4; i++) o[i][dd] = fmaf(pv[i], vv, o[i][dd]);
            }
        }
    }

#pragma unroll
    for (int i = 0; i < 4; i++) {
        int srow = q0 + tr * 4 + i;
        if (srow >= S_) continue;
        float inv = 1.f / l_s[tr * 4 + i];
#pragma unroll
        for (int dd = 0; dd < 5; dd++) {
            float val = o[i][dd] * inv;
            size_t oidx = ((size_t)b * S_ + srow) * D_ + h * HD_ + tc * 5 + dd;
            __nv_bfloat16 hv = __float2bfloat16(val);
            out_hi[oidx] = hv;
            out_lo[oidx] = __float2bfloat16(val - __bfloat162float(hv));
        }
    }
}

// ----------------------------------------------------------------
extern "C" void kernel_launch(void* const* d_in, const int* in_sizes, int n_in,
                              void* d_out, int out_size)
{
    const float* hs = (const float*)d_in[0];
    const float* fc = (const float*)d_in[1];
    const float* fs = (const float*)d_in[2];
    const float* W[4] = { (const float*)d_in[3], (const float*)d_in[5],
                          (const float*)d_in[7], (const float*)d_in[9] };
    const float* bq = (const float*)d_in[4];
    const float* bk = (const float*)d_in[6];
    const float* bv = (const float*)d_in[8];
    const float* bo = (const float*)d_in[10];
    float* out = (float*)d_out;

    float *pq, *pk, *pv;
    __nv_bfloat16 *hshi, *hslo, *whi, *wlo, *athi, *atlo;
    cudaGetSymbolAddress((void**)&pq, g_q);
    cudaGetSymbolAddress((void**)&pk, g_k);
    cudaGetSymbolAddress((void**)&pv, g_v);
    cudaGetSymbolAddress((void**)&hshi, g_hs_hi);
    cudaGetSymbolAddress((void**)&hslo, g_hs_lo);
    cudaGetSymbolAddress((void**)&whi, g_w_hi);
    cudaGetSymbolAddress((void**)&wlo, g_w_lo);
    cudaGetSymbolAddress((void**)&athi, g_at_hi);
    cudaGetSymbolAddress((void**)&atlo, g_at_lo);

    // splits
    {
        int n = M_ * K_;
        split_kernel<<<(n + 255) / 256, 256>>>(hs, hshi, hslo, n);
        int nw = K_ * N_;
        for (int i = 0; i < 4; i++)
            split_kernel<<<(nw + 255) / 256, 256>>>(W[i], whi + (size_t)i * nw,
                                                    wlo + (size_t)i * nw, nw);
    }

    cudaFuncSetAttribute(gemm_hmma, cudaFuncAttributeMaxDynamicSharedMemorySize,
                         GEMM_SMEM);
    dim3 ggrid(N_ / 128, (M_ + 127) / 128);  // (10, 73)
    size_t wsz = (size_t)K_ * N_;

    gemm_hmma<<<ggrid, 256, GEMM_SMEM>>>(hshi, hslo, whi + 0 * wsz, wlo + 0 * wsz,
                                         bq, pq, M_, 1);
    gemm_hmma<<<ggrid, 256, GEMM_SMEM>>>(hshi, hslo, whi + 1 * wsz, wlo + 1 * wsz,
                                         bk, pk, M_, 1);
    gemm_hmma<<<ggrid, 256, GEMM_SMEM>>>(hshi, hslo, whi + 2 * wsz, wlo + 2 * wsz,
                                         bv, pv, M_, 1);

    int pairs = B_ * H_ * S_ * HALF_;
    rope_kernel<<<(pairs + 255) / 256, 256>>>(pq, pk, fc, fs);

    size_t smem = (size_t)(BQ * QS + 2 * BKT * QS + BQ * PS + BQ * 7) * sizeof(float);
    cudaFuncSetAttribute(attn_kernel, cudaFuncAttributeMaxDynamicSharedMemorySize,
                         (int)smem);
    attn_kernel<<<dim3((S_ + BQ - 1) / BQ, H_, B_), 256, smem>>>(pq, pk, pv,
                                                                 athi, atlo);

    gemm_hmma<<<ggrid, 256, GEMM_SMEM>>>(athi, atlo, whi + 3 * wsz, wlo + 3 * wsz,
                                         bo, out, M_, 0);
}

// round 4
// speedup vs baseline: 3.3840x; 1.9616x over previous
#include <cuda_runtime.h>
#include <cuda_bf16.h>
#include <math.h>
#include <stdint.h>

#define B_    16
#define S_    577
#define D_    1280
#define H_    16
#define HD_   80
#define HALF_ 40
#define M_    (B_*S_)   // 9232
#define K_    1280
#define N_    1280

// ---------------------------------------------------------------- scratch
__device__ __align__(16) __nv_bfloat16 g_hs_hi[M_*K_];
__device__ __align__(16) __nv_bfloat16 g_hs_lo[M_*K_];
__device__ __align__(16) __nv_bfloat16 g_w_hi[4*K_*N_];
__device__ __align__(16) __nv_bfloat16 g_w_lo[4*K_*N_];
__device__ __align__(16) __nv_bfloat16 g_at_hi[M_*K_];
__device__ __align__(16) __nv_bfloat16 g_at_lo[M_*K_];
__device__ __align__(16) __nv_bfloat16 g_qhi[B_*H_*S_*HD_];
__device__ __align__(16) __nv_bfloat16 g_qlo[B_*H_*S_*HD_];
__device__ __align__(16) __nv_bfloat16 g_khi[B_*H_*S_*HD_];
__device__ __align__(16) __nv_bfloat16 g_klo[B_*H_*S_*HD_];
__device__ __align__(16) __nv_bfloat16 g_vhi[B_*H_*S_*HD_];
__device__ __align__(16) __nv_bfloat16 g_vlo[B_*H_*S_*HD_];

// ---------------------------------------------------------------- helpers
__device__ __forceinline__ uint32_t smem_u32(const void* p) {
    uint32_t a;
    asm("{ .reg .u64 t; cvta.to.shared.u64 t, %1; cvt.u32.u64 %0, t; }"
        : "=r"(a) : "l"(p));
    return a;
}
__device__ __forceinline__ void cp16(uint32_t dst, const void* src, int sz) {
    asm volatile("cp.async.cg.shared.global [%0], [%1], 16, %2;"
                 :: "r"(dst), "l"(src), "r"(sz) : "memory");
}
#define CP_COMMIT() asm volatile("cp.async.commit_group;" ::: "memory")
#define CP_WAIT0()  asm volatile("cp.async.wait_group 0;" ::: "memory")

__device__ __forceinline__ void ldx4(uint32_t* r, uint32_t addr) {
    asm volatile("ldmatrix.sync.aligned.m8n8.x4.shared.b16 {%0,%1,%2,%3}, [%4];"
                 : "=r"(r[0]), "=r"(r[1]), "=r"(r[2]), "=r"(r[3]) : "r"(addr));
}
__device__ __forceinline__ void ldx4t(uint32_t* r, uint32_t addr) {
    asm volatile("ldmatrix.sync.aligned.m8n8.x4.trans.shared.b16 {%0,%1,%2,%3}, [%4];"
                 : "=r"(r[0]), "=r"(r[1]), "=r"(r[2]), "=r"(r[3]) : "r"(addr));
}
__device__ __forceinline__ void hmma(float* d, const uint32_t* a, const uint32_t* b) {
    asm volatile(
        "mma.sync.aligned.m16n8k16.row.col.f32.bf16.bf16.f32 "
        "{%0,%1,%2,%3}, {%4,%5,%6,%7}, {%8,%9}, {%0,%1,%2,%3};"
        : "+f"(d[0]), "+f"(d[1]), "+f"(d[2]), "+f"(d[3])
        : "r"(a[0]), "r"(a[1]), "r"(a[2]), "r"(a[3]), "r"(b[0]), "r"(b[1]));
}
__device__ __forceinline__ void split2(float x, float y, uint32_t& hi, uint32_t& lo) {
    __nv_bfloat162 h = __floats2bfloat162_rn(x, y);
    float hx = __bfloat162float(h.x), hy = __bfloat162float(h.y);
    __nv_bfloat162 l = __floats2bfloat162_rn(x - hx, y - hy);
    hi = *(uint32_t*)&h; lo = *(uint32_t*)&l;
}

// ---------------------------------------------------------------- fp32 -> bf16 hi/lo split
__global__ __launch_bounds__(256)
void split_kernel(const float* __restrict__ x,
                  __nv_bfloat16* __restrict__ hi,
                  __nv_bfloat16* __restrict__ lo, int n)
{
    int i = blockIdx.x * blockDim.x + threadIdx.x;
    if (i >= n) return;
    float v = x[i];
    __nv_bfloat16 h = __float2bfloat16(v);
    hi[i] = h;
    lo[i] = __float2bfloat16(v - __bfloat162float(h));
}

// ---------------------------------------------------------------- HMMA GEMM
// mode 0: C fp32 [M,N] = acc + bias
// mode 1: rope(acc+bias)*scale -> bf16 hi/lo at (bh, s, d)   [q,k]
// mode 2: (acc+bias) -> bf16 hi/lo at (bh, s, d)             [v]
#define SPADB 80
#define TILEB (128*SPADB)
#define STAGEB (4*TILEB)
#define GEMM_SMEM (2*STAGEB)
#define NIT (K_/32)

__global__ __launch_bounds__(256)
void gemm_hmma(const __nv_bfloat16* __restrict__ Ahi, const __nv_bfloat16* __restrict__ Alo,
               const __nv_bfloat16* __restrict__ Bhi, const __nv_bfloat16* __restrict__ Blo,
               const float* __restrict__ bias, float* __restrict__ Cf,
               __nv_bfloat16* __restrict__ Chi, __nv_bfloat16* __restrict__ Clo,
               const float* __restrict__ fc, const float* __restrict__ fs,
               int M, int mode, float scale)
{
    extern __shared__ __align__(16) char smem[];
    const int tid = threadIdx.x, wid = tid >> 5, lane = tid & 31;
    const int bn = blockIdx.x, bm = blockIdx.y;
    const int wm = wid >> 2, wn = wid & 3;
    const int row0A = bm * 128, row0B = bn * 128;
    const uint32_t sbase = smem_u32(smem);

    float acc[4][4][4];
#pragma unroll
    for (int i = 0; i < 4; i++)
#pragma unroll
        for (int j = 0; j < 4; j++)
#pragma unroll
            for (int c = 0; c < 4; c++) acc[i][j][c] = 0.f;

    auto load_stage = [&](int st, int k0) {
        uint32_t sdst = sbase + st * STAGEB;
#pragma unroll
        for (int t = 0; t < 8; t++) {
            int idx = tid + t * 256;
            int tile = idx >> 9;
            int r = (idx >> 2) & 127;
            int seg = idx & 3;
            uint32_t d = sdst + tile * TILEB + r * SPADB + seg * 16;
            const __nv_bfloat16* sp;
            int sz = 16;
            if (tile < 2) {
                int row = row0A + r;
                if (row >= M) { row = M - 1; sz = 0; }
                sp = (tile == 0 ? Ahi : Alo) + (size_t)row * K_ + k0 + seg * 8;
            } else {
                int row = row0B + r;
                sp = (tile == 2 ? Bhi : Blo) + (size_t)row * K_ + k0 + seg * 8;
            }
            cp16(d, sp, sz);
        }
        CP_COMMIT();
    };

    const uint32_t a_lane = (uint32_t)((wm * 64 + (lane & 15)) * SPADB + (lane >> 4) * 16);
    const uint32_t b_lane = (uint32_t)((wn * 32 + ((lane >> 4) << 3) + (lane & 7)) * SPADB
                                       + ((lane >> 3) & 1) * 16);

    load_stage(0, 0);

    for (int it = 0; it < NIT; it++) {
        int cur = it & 1;
        if (it + 1 < NIT) {
            load_stage(cur ^ 1, (it + 1) * 32);
            asm volatile("cp.async.wait_group 1;" ::: "memory");
        } else {
            CP_WAIT0();
        }
        __syncthreads();

        uint32_t scur = sbase + cur * STAGEB;
#pragma unroll
        for (int kk = 0; kk < 2; kk++) {
            uint32_t ab = scur + a_lane + kk * 32;
            uint32_t bb = scur + 2 * TILEB + b_lane + kk * 32;

            uint32_t ah[4][4], al[4][4], bh[4][2], bl[4][2];
#pragma unroll
            for (int mi = 0; mi < 4; mi++) ldx4(ah[mi], ab + mi * 16 * SPADB);
#pragma unroll
            for (int mi = 0; mi < 4; mi++) ldx4(al[mi], ab + TILEB + mi * 16 * SPADB);
#pragma unroll
            for (int np = 0; np < 2; np++) {
                uint32_t r[4];
                ldx4(r, bb + np * 16 * SPADB);
                bh[np * 2][0] = r[0]; bh[np * 2][1] = r[1];
                bh[np * 2 + 1][0] = r[2]; bh[np * 2 + 1][1] = r[3];
                ldx4(r, bb + TILEB + np * 16 * SPADB);
                bl[np * 2][0] = r[0]; bl[np * 2][1] = r[1];
                bl[np * 2 + 1][0] = r[2]; bl[np * 2 + 1][1] = r[3];
            }
#pragma unroll
            for (int mi = 0; mi < 4; mi++)
#pragma unroll
                for (int ni = 0; ni < 4; ni++) hmma(acc[mi][ni], ah[mi], bh[ni]);
#pragma unroll
            for (int mi = 0; mi < 4; mi++)
#pragma unroll
                for (int ni = 0; ni < 4; ni++) hmma(acc[mi][ni], ah[mi], bl[ni]);
#pragma unroll
            for (int mi = 0; mi < 4; mi++)
#pragma unroll
                for (int ni = 0; ni < 4; ni++) hmma(acc[mi][ni], al[mi], bh[ni]);
        }
        __syncthreads();
    }

    // ---- epilogue ----
    const int mrow = (lane >> 2);
    const int ncol = (lane & 3) * 2;
#pragma unroll
    for (int mi = 0; mi < 4; mi++) {
#pragma unroll
        for (int h2 = 0; h2 < 2; h2++) {
            int m = row0A + wm * 64 + mi * 16 + mrow + h2 * 8;
            if (m >= M) continue;
            int bb2 = m / S_, ss = m - bb2 * S_;
#pragma unroll
            for (int ni = 0; ni < 4; ni++) {
                int n0 = bn * 128 + wn * 32 + ni * 8 + ncol;
                float vx = acc[mi][ni][h2 * 2] + bias[n0];
                float vy = acc[mi][ni][h2 * 2 + 1] + bias[n0 + 1];
                if (mode == 0) {
                    float2 v = make_float2(vx, vy);
                    *(float2*)&Cf[(size_t)m * N_ + n0] = v;
                } else {
                    int h = n0 / HD_, d = n0 - h * HD_;
                    float rx = vx, ry = vy;
                    if (mode == 1) {
                        int j = d >> 1;
                        float c = fc[ss * HALF_ + j], sn = fs[ss * HALF_ + j];
                        rx = (vx * c - vy * sn) * scale;
                        ry = (vx * sn + vy * c) * scale;
                    }
                    uint32_t hi2, lo2;
                    split2(rx, ry, hi2, lo2);
                    size_t idx = ((size_t)(bb2 * H_ + h) * S_ + ss) * HD_ + d;
                    *(uint32_t*)&Chi[idx] = hi2;
                    *(uint32_t*)&Clo[idx] = lo2;
                }
            }
        }
    }
}

// ---------------------------------------------------------------- HMMA flash attention
// CTA: (q-tile of 64, head, batch). 128 threads = 4 warps as 2(M) x 2(Nk).
// QK^T on tensor cores (2-term split), softmax in fragment layout,
// P->A-fragment identity remap, PV with warp k-split + end reduction.
#define SVB 176                   // bytes per smem row (80 bf16 + 8 pad)
#define ATT_TILE (64*SVB)         // 11264
#define ATT_SMEM (6*ATT_TILE + 64*4*3 + 128*4*2)

__global__ __launch_bounds__(128)
void attn_hmma(const __nv_bfloat16* __restrict__ qhi, const __nv_bfloat16* __restrict__ qlo,
               const __nv_bfloat16* __restrict__ khi, const __nv_bfloat16* __restrict__ klo,
               const __nv_bfloat16* __restrict__ vhi, const __nv_bfloat16* __restrict__ vlo,
               __nv_bfloat16* __restrict__ at_hi, __nv_bfloat16* __restrict__ at_lo)
{
    extern __shared__ __align__(16) char smem[];
    const uint32_t sb = smem_u32(smem);
    float* m_s  = (float*)(smem + 6 * ATT_TILE);
    float* l_s  = m_s + 64;
    float* al_s = l_s + 64;
    float* redm = al_s + 64;   // [64][2]
    float* reds = redm + 128;  // [64][2]

    const int tid = threadIdx.x, wid = tid >> 5, lane = tid & 31;
    const int wm = wid >> 1, wn = wid & 1;
    const int qt = blockIdx.x, h = blockIdx.y, b = blockIdx.z;
    const int bh = b * H_ + h;
    const size_t off = (size_t)bh * S_ * HD_;
    const int q0 = qt * 64;

    // ---- load Q hi/lo (rows q0..q0+63) ----
#pragma unroll
    for (int t = 0; t < 10; t++) {
        int i = tid + t * 128;            // 0..1279
        int tile = i / 640;               // 0=hi,1=lo
        int rr = (i % 640) / 10, seg = i % 10;
        int row = q0 + rr;
        int sz = (row < S_) ? 16 : 0;
        if (row >= S_) row = S_ - 1;
        const __nv_bfloat16* sp = (tile ? qlo : qhi) + off + (size_t)row * HD_ + seg * 8;
        cp16(sb + tile * ATT_TILE + rr * SVB + seg * 16, sp, sz);
    }
    CP_COMMIT();

    if (tid < 64) { m_s[tid] = -1e30f; l_s[tid] = 0.f; }

    float out[2][10][4];
#pragma unroll
    for (int mi = 0; mi < 2; mi++)
#pragma unroll
        for (int ni = 0; ni < 10; ni++)
#pragma unroll
            for (int c = 0; c < 4; c++) out[mi][ni][c] = 0.f;

    const int r0 = lane >> 2, c0 = (lane & 3) * 2;

    for (int kt = 0; kt < 10; kt++) {
        __syncthreads();   // all warps done with previous K/V
        // ---- load K,V hi/lo (rows kt*64 .. +63) ----
#pragma unroll
        for (int t = 0; t < 20; t++) {
            int i = tid + t * 128;        // 0..2559
            int tile = i / 640;           // 0 Khi,1 Klo,2 Vhi,3 Vlo
            int rr = (i % 640) / 10, seg = i % 10;
            int row = kt * 64 + rr;
            int sz = (row < S_) ? 16 : 0;
            if (row >= S_) row = S_ - 1;
            const __nv_bfloat16* sp =
                (tile == 0 ? khi : tile == 1 ? klo : tile == 2 ? vhi : vlo)
                + off + (size_t)row * HD_ + seg * 8;
            cp16(sb + (2 + tile) * ATT_TILE + rr * SVB + seg * 16, sp, sz);
        }
        CP_COMMIT();
        CP_WAIT0();
        __syncthreads();

        // ---- QK^T: warp tile 32(M) x 32(N), k = 80 ----
        float sacc[2][4][4];
#pragma unroll
        for (int mi = 0; mi < 2; mi++)
#pragma unroll
            for (int ni = 0; ni < 4; ni++)
#pragma unroll
                for (int c = 0; c < 4; c++) sacc[mi][ni][c] = 0.f;

#pragma unroll
        for (int k16 = 0; k16 < 5; k16++) {
            uint32_t ah[2][4], al[2][4], bh2[4][2], bl2[4][2];
            uint32_t abase = sb + (wm * 32 + (lane & 15)) * SVB + (lane >> 4) * 16 + k16 * 32;
#pragma unroll
            for (int mi = 0; mi < 2; mi++) {
                ldx4(ah[mi], abase + mi * 16 * SVB);
                ldx4(al[mi], abase + ATT_TILE + mi * 16 * SVB);
            }
            uint32_t bbase = sb + 2 * ATT_TILE
                           + (wn * 32 + ((lane >> 4) << 3) + (lane & 7)) * SVB
                           + ((lane >> 3) & 1) * 16 + k16 * 32;
#pragma unroll
            for (int nt = 0; nt < 2; nt++) {
                uint32_t r[4];
                ldx4(r, bbase + nt * 16 * SVB);
                bh2[nt * 2][0] = r[0]; bh2[nt * 2][1] = r[1];
                bh2[nt * 2 + 1][0] = r[2]; bh2[nt * 2 + 1][1] = r[3];
                ldx4(r, bbase + ATT_TILE + nt * 16 * SVB);
                bl2[nt * 2][0] = r[0]; bl2[nt * 2][1] = r[1];
                bl2[nt * 2 + 1][0] = r[2]; bl2[nt * 2 + 1][1] = r[3];
            }
#pragma unroll
            for (int mi = 0; mi < 2; mi++)
#pragma unroll
                for (int ni = 0; ni < 4; ni++) {
                    hmma(sacc[mi][ni], ah[mi], bh2[ni]);
                    hmma(sacc[mi][ni], ah[mi], bl2[ni]);
                    hmma(sacc[mi][ni], al[mi], bh2[ni]);
                }
        }

        // ---- mask + row max ----
        float mloc[2][2] = {{-1e30f, -1e30f}, {-1e30f, -1e30f}};
#pragma unroll
        for (int mi = 0; mi < 2; mi++)
#pragma unroll
            for (int ni = 0; ni < 4; ni++)
#pragma unroll
                for (int h8 = 0; h8 < 2; h8++)
#pragma unroll
                    for (int j = 0; j < 2; j++) {
                        int key = kt * 64 + wn * 32 + ni * 8 + c0 + j;
                        float sv = (key < S_) ? sacc[mi][ni][h8 * 2 + j] : -1e30f;
                        sacc[mi][ni][h8 * 2 + j] = sv;
                        mloc[mi][h8] = fmaxf(mloc[mi][h8], sv);
                    }
#pragma unroll
        for (int mi = 0; mi < 2; mi++)
#pragma unroll
            for (int h8 = 0; h8 < 2; h8++) {
                mloc[mi][h8] = fmaxf(mloc[mi][h8], __shfl_xor_sync(0xffffffffu, mloc[mi][h8], 1));
                mloc[mi][h8] = fmaxf(mloc[mi][h8], __shfl_xor_sync(0xffffffffu, mloc[mi][h8], 2));
            }
        if ((lane & 3) == 0) {
#pragma unroll
            for (int mi = 0; mi < 2; mi++)
#pragma unroll
                for (int h8 = 0; h8 < 2; h8++)
                    redm[(wm * 32 + mi * 16 + r0 + h8 * 8) * 2 + wn] = mloc[mi][h8];
        }
        __syncthreads();
        if (wn == 0) {
            int row = wm * 32 + lane;
            float mn = fmaxf(fmaxf(redm[row * 2], redm[row * 2 + 1]), m_s[row]);
            al_s[row] = __expf(m_s[row] - mn);
            m_s[row] = mn;
        }
        __syncthreads();

        // ---- exp + row sum + rescale out ----
        float mn4[2][2], a4[2][2];
#pragma unroll
        for (int mi = 0; mi < 2; mi++)
#pragma unroll
            for (int h8 = 0; h8 < 2; h8++) {
                int row = wm * 32 + mi * 16 + r0 + h8 * 8;
                mn4[mi][h8] = m_s[row];
                a4[mi][h8] = al_s[row];
            }
        float sl[2][2] = {{0.f, 0.f}, {0.f, 0.f}};
#pragma unroll
        for (int mi = 0; mi < 2; mi++)
#pragma unroll
            for (int ni = 0; ni < 4; ni++)
#pragma unroll
                for (int h8 = 0; h8 < 2; h8++)
#pragma unroll
                    for (int j = 0; j < 2; j++) {
                        float e = __expf(sacc[mi][ni][h8 * 2 + j] - mn4[mi][h8]);
                        sacc[mi][ni][h8 * 2 + j] = e;
                        sl[mi][h8] += e;
                    }
#pragma unroll
        for (int mi = 0; mi < 2; mi++)
#pragma unroll
            for (int h8 = 0; h8 < 2; h8++) {
                sl[mi][h8] += __shfl_xor_sync(0xffffffffu, sl[mi][h8], 1);
                sl[mi][h8] += __shfl_xor_sync(0xffffffffu, sl[mi][h8], 2);
            }
        if ((lane & 3) == 0) {
#pragma unroll
            for (int mi = 0; mi < 2; mi++)
#pragma unroll
                for (int h8 = 0; h8 < 2; h8++)
                    reds[(wm * 32 + mi * 16 + r0 + h8 * 8) * 2 + wn] = sl[mi][h8];
        }
#pragma unroll
        for (int mi = 0; mi < 2; mi++)
#pragma unroll
            for (int ni = 0; ni < 10; ni++)
#pragma unroll
                for (int h8 = 0; h8 < 2; h8++) {
                    out[mi][ni][h8 * 2]     *= a4[mi][h8];
                    out[mi][ni][h8 * 2 + 1] *= a4[mi][h8];
                }
        __syncthreads();
        if (wn == 0) {
            int row = wm * 32 + lane;
            l_s[row] = l_s[row] * al_s[row] + reds[row * 2] + reds[row * 2 + 1];
        }

        // ---- PV: P fragments direct from sacc; warp k-slice = its 32 score cols ----
#pragma unroll
        for (int kk = 0; kk < 2; kk++) {
            uint32_t pa_h[2][4], pa_l[2][4];
            int tni = kk * 2;
#pragma unroll
            for (int mi = 0; mi < 2; mi++) {
                split2(sacc[mi][tni][0], sacc[mi][tni][1], pa_h[mi][0], pa_l[mi][0]);
                split2(sacc[mi][tni][2], sacc[mi][tni][3], pa_h[mi][1], pa_l[mi][1]);
                split2(sacc[mi][tni + 1][0], sacc[mi][tni + 1][1], pa_h[mi][2], pa_l[mi][2]);
                split2(sacc[mi][tni + 1][2], sacc[mi][tni + 1][3], pa_h[mi][3], pa_l[mi][3]);
            }
            uint32_t vbase = sb + 4 * ATT_TILE
                           + (wn * 32 + kk * 16 + (lane & 15)) * SVB + (lane >> 4) * 16;
#pragma unroll
            for (int nt = 0; nt < 5; nt++) {
                uint32_t rh[4], rl[4];
                ldx4t(rh, vbase + nt * 32);
                ldx4t(rl, vbase + ATT_TILE + nt * 32);
                uint32_t vbh0[2] = {rh[0], rh[1]}, vbh1[2] = {rh[2], rh[3]};
                uint32_t vbl0[2] = {rl[0], rl[1]}, vbl1[2] = {rl[2], rl[3]};
#pragma unroll
                for (int mi = 0; mi < 2; mi++) {
                    hmma(out[mi][nt * 2], pa_h[mi], vbh0);
                    hmma(out[mi][nt * 2], pa_h[mi], vbl0);
                    hmma(out[mi][nt * 2], pa_l[mi], vbh0);
                    hmma(out[mi][nt * 2 + 1], pa_h[mi], vbh1);
                    hmma(out[mi][nt * 2 + 1], pa_h[mi], vbl1);
                    hmma(out[mi][nt * 2 + 1], pa_l[mi], vbh1);
                }
            }
        }
    }

    // ---- cross-warp (wn) reduction + normalize + write ----
    __syncthreads();
    float* stage = (float*)smem;   // reuse Q region (>= 64*84*4 bytes)
    if (wn == 1) {
#pragma unroll
        for (int mi = 0; mi < 2; mi++)
#pragma unroll
            for (int ni = 0; ni < 10; ni++)
#pragma unroll
                for (int h8 = 0; h8 < 2; h8++) {
                    int row = wm * 32 + mi * 16 + r0 + h8 * 8;
                    int col = ni * 8 + c0;
                    stage[row * 84 + col] = out[mi][ni][h8 * 2];
                    stage[row * 84 + col + 1] = out[mi][ni][h8 * 2 + 1];
                }
    }
    __syncthreads();
    if (wn == 0) {
#pragma unroll
        for (int mi = 0; mi < 2; mi++)
#pragma unroll
            for (int h8 = 0; h8 < 2; h8++) {
                int row = wm * 32 + mi * 16 + r0 + h8 * 8;
                int srow = q0 + row;
                if (srow >= S_) continue;
                float rl = 1.f / l_s[row];
#pragma unroll
                for (int ni = 0; ni < 10; ni++) {
                    int col = ni * 8 + c0;
                    float vx = (out[mi][ni][h8 * 2] + stage[row * 84 + col]) * rl;
                    float vy = (out[mi][ni][h8 * 2 + 1] + stage[row * 84 + col + 1]) * rl;
                    uint32_t hi2, lo2;
                    split2(vx, vy, hi2, lo2);
                    size_t oidx = ((size_t)b * S_ + srow) * D_ + h * HD_ + col;
                    *(uint32_t*)&at_hi[oidx] = hi2;
                    *(uint32_t*)&at_lo[oidx] = lo2;
                }
            }
    }
}

// ----------------------------------------------------------------
extern "C" void kernel_launch(void* const* d_in, const int* in_sizes, int n_in,
                              void* d_out, int out_size)
{
    const float* hs = (const float*)d_in[0];
    const float* fc = (const float*)d_in[1];
    const float* fs = (const float*)d_in[2];
    const float* W[4] = { (const float*)d_in[3], (const float*)d_in[5],
                          (const float*)d_in[7], (const float*)d_in[9] };
    const float* bq = (const float*)d_in[4];
    const float* bk = (const float*)d_in[6];
    const float* bv = (const float*)d_in[8];
    const float* bo = (const float*)d_in[10];
    float* out = (float*)d_out;

    __nv_bfloat16 *hshi, *hslo, *whi, *wlo, *athi, *atlo;
    __nv_bfloat16 *qhi, *qlo, *khi, *klo, *vhi, *vlo;
    cudaGetSymbolAddress((void**)&hshi, g_hs_hi);
    cudaGetSymbolAddress((void**)&hslo, g_hs_lo);
    cudaGetSymbolAddress((void**)&whi, g_w_hi);
    cudaGetSymbolAddress((void**)&wlo, g_w_lo);
    cudaGetSymbolAddress((void**)&athi, g_at_hi);
    cudaGetSymbolAddress((void**)&atlo, g_at_lo);
    cudaGetSymbolAddress((void**)&qhi, g_qhi);
    cudaGetSymbolAddress((void**)&qlo, g_qlo);
    cudaGetSymbolAddress((void**)&khi, g_khi);
    cudaGetSymbolAddress((void**)&klo, g_klo);
    cudaGetSymbolAddress((void**)&vhi, g_vhi);
    cudaGetSymbolAddress((void**)&vlo, g_vlo);

    {
        int n = M_ * K_;
        split_kernel<<<(n + 255) / 256, 256>>>(hs, hshi, hslo, n);
        int nw = K_ * N_;
        for (int i = 0; i < 4; i++)
            split_kernel<<<(nw + 255) / 256, 256>>>(W[i], whi + (size_t)i * nw,
                                                    wlo + (size_t)i * nw, nw);
    }

    cudaFuncSetAttribute(gemm_hmma, cudaFuncAttributeMaxDynamicSharedMemorySize,
                         GEMM_SMEM);
    dim3 ggrid(N_ / 128, (M_ + 127) / 128);
    size_t wsz = (size_t)K_ * N_;
    const float rscale = 0.11180339887498949f;  // 1/sqrt(80)

    gemm_hmma<<<ggrid, 256, GEMM_SMEM>>>(hshi, hslo, whi + 0 * wsz, wlo + 0 * wsz,
                                         bq, nullptr, qhi, qlo, fc, fs, M_, 1, rscale);
    gemm_hmma<<<ggrid, 256, GEMM_SMEM>>>(hshi, hslo, whi + 1 * wsz, wlo + 1 * wsz,
                                         bk, nullptr, khi, klo, fc, fs, M_, 1, 1.0f);
    gemm_hmma<<<ggrid, 256, GEMM_SMEM>>>(hshi, hslo, whi + 2 * wsz, wlo + 2 * wsz,
                                         bv, nullptr, vhi, vlo, fc, fs, M_, 2, 1.0f);

    cudaFuncSetAttribute(attn_hmma, cudaFuncAttributeMaxDynamicSharedMemorySize,
                         ATT_SMEM);
    attn_hmma<<<dim3(10, H_, B_), 128, ATT_SMEM>>>(qhi, qlo, khi, klo, vhi, vlo,
                                                   athi, atlo);

    gemm_hmma<<<ggrid, 256, GEMM_SMEM>>>(athi, atlo, whi + 3 * wsz, wlo + 3 * wsz,
                                         bo, out, nullptr, nullptr, fc, fs, M_, 0, 1.0f);
}

// round 5
// speedup vs baseline: 3.5044x; 1.0356x over previous
#include <cuda_runtime.h>
#include <cuda_bf16.h>
#include <math.h>
#include <stdint.h>

#define B_    16
#define S_    577
#define D_    1280
#define H_    16
#define HD_   80
#define HALF_ 40
#define M_    (B_*S_)   // 9232
#define K_    1280
#define N_    1280

// ---------------------------------------------------------------- scratch
__device__ __align__(16) __nv_bfloat16 g_hs_hi[M_*K_];
__device__ __align__(16) __nv_bfloat16 g_hs_lo[M_*K_];
__device__ __align__(16) __nv_bfloat16 g_w_hi[4*K_*N_];
__device__ __align__(16) __nv_bfloat16 g_w_lo[4*K_*N_];
__device__ __align__(16) __nv_bfloat16 g_at_hi[M_*K_];
__device__ __align__(16) __nv_bfloat16 g_at_lo[M_*K_];
__device__ __align__(16) __nv_bfloat16 g_qhi[B_*H_*S_*HD_];
__device__ __align__(16) __nv_bfloat16 g_qlo[B_*H_*S_*HD_];
__device__ __align__(16) __nv_bfloat16 g_khi[B_*H_*S_*HD_];
__device__ __align__(16) __nv_bfloat16 g_klo[B_*H_*S_*HD_];
__device__ __align__(16) __nv_bfloat16 g_vhi[B_*H_*S_*HD_];
__device__ __align__(16) __nv_bfloat16 g_vlo[B_*H_*S_*HD_];

// ---------------------------------------------------------------- helpers
__device__ __forceinline__ uint32_t smem_u32(const void* p) {
    uint32_t a;
    asm("{ .reg .u64 t; cvta.to.shared.u64 t, %1; cvt.u32.u64 %0, t; }"
        : "=r"(a) : "l"(p));
    return a;
}
__device__ __forceinline__ void cp16(uint32_t dst, const void* src, int sz) {
    asm volatile("cp.async.cg.shared.global [%0], [%1], 16, %2;"
                 :: "r"(dst), "l"(src), "r"(sz) : "memory");
}
#define CP_COMMIT() asm volatile("cp.async.commit_group;" ::: "memory")
#define CP_WAIT0()  asm volatile("cp.async.wait_group 0;" ::: "memory")

__device__ __forceinline__ void ldx4(uint32_t* r, uint32_t addr) {
    asm volatile("ldmatrix.sync.aligned.m8n8.x4.shared.b16 {%0,%1,%2,%3}, [%4];"
                 : "=r"(r[0]), "=r"(r[1]), "=r"(r[2]), "=r"(r[3]) : "r"(addr));
}
__device__ __forceinline__ void ldx4t(uint32_t* r, uint32_t addr) {
    asm volatile("ldmatrix.sync.aligned.m8n8.x4.trans.shared.b16 {%0,%1,%2,%3}, [%4];"
                 : "=r"(r[0]), "=r"(r[1]), "=r"(r[2]), "=r"(r[3]) : "r"(addr));
}
__device__ __forceinline__ void hmma(float* d, const uint32_t* a, const uint32_t* b) {
    asm volatile(
        "mma.sync.aligned.m16n8k16.row.col.f32.bf16.bf16.f32 "
        "{%0,%1,%2,%3}, {%4,%5,%6,%7}, {%8,%9}, {%0,%1,%2,%3};"
        : "+f"(d[0]), "+f"(d[1]), "+f"(d[2]), "+f"(d[3])
        : "r"(a[0]), "r"(a[1]), "r"(a[2]), "r"(a[3]), "r"(b[0]), "r"(b[1]));
}
__device__ __forceinline__ void split2(float x, float y, uint32_t& hi, uint32_t& lo) {
    __nv_bfloat162 h = __floats2bfloat162_rn(x, y);
    float hx = __bfloat162float(h.x), hy = __bfloat162float(h.y);
    __nv_bfloat162 l = __floats2bfloat162_rn(x - hx, y - hy);
    hi = *(uint32_t*)&h; lo = *(uint32_t*)&l;
}

// ---------------------------------------------------------------- fp32 -> bf16 hi/lo split
__global__ __launch_bounds__(256)
void split_kernel(const float* __restrict__ x,
                  __nv_bfloat16* __restrict__ hi,
                  __nv_bfloat16* __restrict__ lo, int n)
{
    int i = blockIdx.x * blockDim.x + threadIdx.x;
    if (i >= n) return;
    float v = x[i];
    __nv_bfloat16 h = __float2bfloat16(v);
    hi[i] = h;
    lo[i] = __float2bfloat16(v - __bfloat162float(h));
}

// ---------------------------------------------------------------- HMMA GEMM
// MODE 0: O-projection, fp32 out [M,1280]
// MODE 1: fused QKV (grid.x = 30); epilogue: rope/scale/split per matrix
#define SPADB 80
#define TILEB (128*SPADB)
#define STAGEB (4*TILEB)
#define GEMM_SMEM (2*STAGEB)
#define NIT (K_/32)

template<int MODE>
__global__ __launch_bounds__(256, 2)
void gemm_hmma(const __nv_bfloat16* __restrict__ Ahi, const __nv_bfloat16* __restrict__ Alo,
               const __nv_bfloat16* __restrict__ Bhi, const __nv_bfloat16* __restrict__ Blo,
               const float* __restrict__ bq, const float* __restrict__ bk,
               const float* __restrict__ bv,
               float* __restrict__ Cf,
               __nv_bfloat16* __restrict__ qhi, __nv_bfloat16* __restrict__ qlo,
               __nv_bfloat16* __restrict__ khi, __nv_bfloat16* __restrict__ klo,
               __nv_bfloat16* __restrict__ vhi, __nv_bfloat16* __restrict__ vlo,
               const float* __restrict__ fc, const float* __restrict__ fs,
               int M)
{
    extern __shared__ __align__(16) char smem[];
    const int tid = threadIdx.x, wid = tid >> 5, lane = tid & 31;
    const int bn = blockIdx.x, bm = blockIdx.y;
    const int wm = wid >> 2, wn = wid & 3;
    const int row0A = bm * 128, row0B = bn * 128;
    const uint32_t sbase = smem_u32(smem);

    float acc[4][4][4];
#pragma unroll
    for (int i = 0; i < 4; i++)
#pragma unroll
        for (int j = 0; j < 4; j++)
#pragma unroll
            for (int c = 0; c < 4; c++) acc[i][j][c] = 0.f;

    auto load_stage = [&](int st, int k0) {
        uint32_t sdst = sbase + st * STAGEB;
#pragma unroll
        for (int t = 0; t < 8; t++) {
            int idx = tid + t * 256;
            int tile = idx >> 9;
            int r = (idx >> 2) & 127;
            int seg = idx & 3;
            uint32_t d = sdst + tile * TILEB + r * SPADB + seg * 16;
            const __nv_bfloat16* sp;
            int sz = 16;
            if (tile < 2) {
                int row = row0A + r;
                if (row >= M) { row = M - 1; sz = 0; }
                sp = (tile == 0 ? Ahi : Alo) + (size_t)row * K_ + k0 + seg * 8;
            } else {
                int row = row0B + r;
                sp = (tile == 2 ? Bhi : Blo) + (size_t)row * K_ + k0 + seg * 8;
            }
            cp16(d, sp, sz);
        }
        CP_COMMIT();
    };

    const uint32_t a_lane = (uint32_t)((wm * 64 + (lane & 15)) * SPADB + (lane >> 4) * 16);
    const uint32_t b_lane = (uint32_t)((wn * 32 + ((lane >> 4) << 3) + (lane & 7)) * SPADB
                                       + ((lane >> 3) & 1) * 16);

    load_stage(0, 0);

    for (int it = 0; it < NIT; it++) {
        int cur = it & 1;
        if (it + 1 < NIT) {
            load_stage(cur ^ 1, (it + 1) * 32);
            asm volatile("cp.async.wait_group 1;" ::: "memory");
        } else {
            CP_WAIT0();
        }
        __syncthreads();

        uint32_t scur = sbase + cur * STAGEB;
#pragma unroll
        for (int kk = 0; kk < 2; kk++) {
            uint32_t ab = scur + a_lane + kk * 32;
            uint32_t bb = scur + 2 * TILEB + b_lane + kk * 32;

            uint32_t af[4][4], bh[4][2], bl[4][2];
#pragma unroll
            for (int mi = 0; mi < 4; mi++) ldx4(af[mi], ab + mi * 16 * SPADB);
#pragma unroll
            for (int np = 0; np < 2; np++) {
                uint32_t r[4];
                ldx4(r, bb + np * 16 * SPADB);
                bh[np * 2][0] = r[0]; bh[np * 2][1] = r[1];
                bh[np * 2 + 1][0] = r[2]; bh[np * 2 + 1][1] = r[3];
                ldx4(r, bb + TILEB + np * 16 * SPADB);
                bl[np * 2][0] = r[0]; bl[np * 2][1] = r[1];
                bl[np * 2 + 1][0] = r[2]; bl[np * 2 + 1][1] = r[3];
            }
            // pass 1: Ahi * Bhi ; pass 2: Ahi * Blo
#pragma unroll
            for (int mi = 0; mi < 4; mi++)
#pragma unroll
                for (int ni = 0; ni < 4; ni++) hmma(acc[mi][ni], af[mi], bh[ni]);
#pragma unroll
            for (int mi = 0; mi < 4; mi++)
#pragma unroll
                for (int ni = 0; ni < 4; ni++) hmma(acc[mi][ni], af[mi], bl[ni]);
            // overwrite A fragments with Alo; pass 3: Alo * Bhi
#pragma unroll
            for (int mi = 0; mi < 4; mi++) ldx4(af[mi], ab + TILEB + mi * 16 * SPADB);
#pragma unroll
            for (int mi = 0; mi < 4; mi++)
#pragma unroll
                for (int ni = 0; ni < 4; ni++) hmma(acc[mi][ni], af[mi], bh[ni]);
        }
        __syncthreads();
    }

    // ---- epilogue ----
    const int mrow = (lane >> 2);
    const int ncol = (lane & 3) * 2;

    const float rscale = 0.11180339887498949f;  // 1/sqrt(80)
    int mat = 0;
    const float* bias = bq;
    __nv_bfloat16 *Chi = qhi, *Clo = qlo;
    float scale = 1.f;
    bool dorope = false;
    if (MODE == 1) {
        mat = bn / 10;
        bias = (mat == 0) ? bq : (mat == 1) ? bk : bv;
        Chi = (mat == 0) ? qhi : (mat == 1) ? khi : vhi;
        Clo = (mat == 0) ? qlo : (mat == 1) ? klo : vlo;
        scale = (mat == 0) ? rscale : 1.f;
        dorope = (mat < 2);
    }
    const int nbase = (MODE == 1) ? (bn % 10) * 128 : bn * 128;

#pragma unroll
    for (int mi = 0; mi < 4; mi++) {
#pragma unroll
        for (int h2 = 0; h2 < 2; h2++) {
            int m = row0A + wm * 64 + mi * 16 + mrow + h2 * 8;
            if (m >= M) continue;
            int bb2 = m / S_, ss = m - bb2 * S_;
#pragma unroll
            for (int ni = 0; ni < 4; ni++) {
                int n0 = nbase + wn * 32 + ni * 8 + ncol;
                float vx = acc[mi][ni][h2 * 2] + bias[n0];
                float vy = acc[mi][ni][h2 * 2 + 1] + bias[n0 + 1];
                if (MODE == 0) {
                    float2 v = make_float2(vx, vy);
                    *(float2*)&Cf[(size_t)m * N_ + n0] = v;
                } else {
                    int h = n0 / HD_, d = n0 - h * HD_;
                    float rx = vx, ry = vy;
                    if (dorope) {
                        int j = d >> 1;
                        float c = fc[ss * HALF_ + j], sn = fs[ss * HALF_ + j];
                        rx = (vx * c - vy * sn) * scale;
                        ry = (vx * sn + vy * c) * scale;
                    }
                    uint32_t hi2, lo2;
                    split2(rx, ry, hi2, lo2);
                    size_t idx = ((size_t)(bb2 * H_ + h) * S_ + ss) * HD_ + d;
                    *(uint32_t*)&Chi[idx] = hi2;
                    *(uint32_t*)&Clo[idx] = lo2;
                }
            }
        }
    }
}

// ---------------------------------------------------------------- HMMA flash attention
#define SVB 176                   // bytes per smem row (80 bf16 + 8 pad)
#define ATT_TILE (64*SVB)         // 11264
#define ATT_SMEM (6*ATT_TILE + 64*4*3 + 128*4*2)

__global__ __launch_bounds__(128)
void attn_hmma(const __nv_bfloat16* __restrict__ qhi, const __nv_bfloat16* __restrict__ qlo,
               const __nv_bfloat16* __restrict__ khi, const __nv_bfloat16* __restrict__ klo,
               const __nv_bfloat16* __restrict__ vhi, const __nv_bfloat16* __restrict__ vlo,
               __nv_bfloat16* __restrict__ at_hi, __nv_bfloat16* __restrict__ at_lo)
{
    extern __shared__ __align__(16) char smem[];
    const uint32_t sb = smem_u32(smem);
    float* m_s  = (float*)(smem + 6 * ATT_TILE);
    float* l_s  = m_s + 64;
    float* al_s = l_s + 64;
    float* redm = al_s + 64;   // [64][2]
    float* reds = redm + 128;  // [64][2]

    const int tid = threadIdx.x, wid = tid >> 5, lane = tid & 31;
    const int wm = wid >> 1, wn = wid & 1;
    const int qt = blockIdx.x, h = blockIdx.y, b = blockIdx.z;
    const int bh = b * H_ + h;
    const size_t off = (size_t)bh * S_ * HD_;
    const int q0 = qt * 64;

#pragma unroll
    for (int t = 0; t < 10; t++) {
        int i = tid + t * 128;
        int tile = i / 640;
        int rr = (i % 640) / 10, seg = i % 10;
        int row = q0 + rr;
        int sz = (row < S_) ? 16 : 0;
        if (row >= S_) row = S_ - 1;
        const __nv_bfloat16* sp = (tile ? qlo : qhi) + off + (size_t)row * HD_ + seg * 8;
        cp16(sb + tile * ATT_TILE + rr * SVB + seg * 16, sp, sz);
    }
    CP_COMMIT();

    if (tid < 64) { m_s[tid] = -1e30f; l_s[tid] = 0.f; }

    float out[2][10][4];
#pragma unroll
    for (int mi = 0; mi < 2; mi++)
#pragma unroll
        for (int ni = 0; ni < 10; ni++)
#pragma unroll
            for (int c = 0; c < 4; c++) out[mi][ni][c] = 0.f;

    const int r0 = lane >> 2, c0 = (lane & 3) * 2;

    for (int kt = 0; kt < 10; kt++) {
        __syncthreads();
#pragma unroll
        for (int t = 0; t < 20; t++) {
            int i = tid + t * 128;
            int tile = i / 640;
            int rr = (i % 640) / 10, seg = i % 10;
            int row = kt * 64 + rr;
            int sz = (row < S_) ? 16 : 0;
            if (row >= S_) row = S_ - 1;
            const __nv_bfloat16* sp =
                (tile == 0 ? khi : tile == 1 ? klo : tile == 2 ? vhi : vlo)
                + off + (size_t)row * HD_ + seg * 8;
            cp16(sb + (2 + tile) * ATT_TILE + rr * SVB + seg * 16, sp, sz);
        }
        CP_COMMIT();
        CP_WAIT0();
        __syncthreads();

        float sacc[2][4][4];
#pragma unroll
        for (int mi = 0; mi < 2; mi++)
#pragma unroll
            for (int ni = 0; ni < 4; ni++)
#pragma unroll
                for (int c = 0; c < 4; c++) sacc[mi][ni][c] = 0.f;

#pragma unroll
        for (int k16 = 0; k16 < 5; k16++) {
            uint32_t ah[2][4], al[2][4], bh2[4][2], bl2[4][2];
            uint32_t abase = sb + (wm * 32 + (lane & 15)) * SVB + (lane >> 4) * 16 + k16 * 32;
#pragma unroll
            for (int mi = 0; mi < 2; mi++) {
                ldx4(ah[mi], abase + mi * 16 * SVB);
                ldx4(al[mi], abase + ATT_TILE + mi * 16 * SVB);
            }
            uint32_t bbase = sb + 2 * ATT_TILE
                           + (wn * 32 + ((lane >> 4) << 3) + (lane & 7)) * SVB
                           + ((lane >> 3) & 1) * 16 + k16 * 32;
#pragma unroll
            for (int nt = 0; nt < 2; nt++) {
                uint32_t r[4];
                ldx4(r, bbase + nt * 16 * SVB);
                bh2[nt * 2][0] = r[0]; bh2[nt * 2][1] = r[1];
                bh2[nt * 2 + 1][0] = r[2]; bh2[nt * 2 + 1][1] = r[3];
                ldx4(r, bbase + ATT_TILE + nt * 16 * SVB);
                bl2[nt * 2][0] = r[0]; bl2[nt * 2][1] = r[1];
                bl2[nt * 2 + 1][0] = r[2]; bl2[nt * 2 + 1][1] = r[3];
            }
#pragma unroll
            for (int mi = 0; mi < 2; mi++)
#pragma unroll
                for (int ni = 0; ni < 4; ni++) {
                    hmma(sacc[mi][ni], ah[mi], bh2[ni]);
                    hmma(sacc[mi][ni], ah[mi], bl2[ni]);
                    hmma(sacc[mi][ni], al[mi], bh2[ni]);
                }
        }

        float mloc[2][2] = {{-1e30f, -1e30f}, {-1e30f, -1e30f}};
#pragma unroll
        for (int mi = 0; mi < 2; mi++)
#pragma unroll
            for (int ni = 0; ni < 4; ni++)
#pragma unroll
                for (int h8 = 0; h8 < 2; h8++)
#pragma unroll
                    for (int j = 0; j < 2; j++) {
                        int key = kt * 64 + wn * 32 + ni * 8 + c0 + j;
                        float sv = (key < S_) ? sacc[mi][ni][h8 * 2 + j] : -1e30f;
                        sacc[mi][ni][h8 * 2 + j] = sv;
                        mloc[mi][h8] = fmaxf(mloc[mi][h8], sv);
                    }
#pragma unroll
        for (int mi = 0; mi < 2; mi++)
#pragma unroll
            for (int h8 = 0; h8 < 2; h8++) {
                mloc[mi][h8] = fmaxf(mloc[mi][h8], __shfl_xor_sync(0xffffffffu, mloc[mi][h8], 1));
                mloc[mi][h8] = fmaxf(mloc[mi][h8], __shfl_xor_sync(0xffffffffu, mloc[mi][h8], 2));
            }
        if ((lane & 3) == 0) {
#pragma unroll
            for (int mi = 0; mi < 2; mi++)
#pragma unroll
                for (int h8 = 0; h8 < 2; h8++)
                    redm[(wm * 32 + mi * 16 + r0 + h8 * 8) * 2 + wn] = mloc[mi][h8];
        }
        __syncthreads();
        if (wn == 0) {
            int row = wm * 32 + lane;
            float mn = fmaxf(fmaxf(redm[row * 2], redm[row * 2 + 1]), m_s[row]);
            al_s[row] = __expf(m_s[row] - mn);
            m_s[row] = mn;
        }
        __syncthreads();

        float mn4[2][2], a4[2][2];
#pragma unroll
        for (int mi = 0; mi < 2; mi++)
#pragma unroll
            for (int h8 = 0; h8 < 2; h8++) {
                int row = wm * 32 + mi * 16 + r0 + h8 * 8;
                mn4[mi][h8] = m_s[row];
                a4[mi][h8] = al_s[row];
            }
        float sl[2][2] = {{0.f, 0.f}, {0.f, 0.f}};
#pragma unroll
        for (int mi = 0; mi < 2; mi++)
#pragma unroll
            for (int ni = 0; ni < 4; ni++)
#pragma unroll
                for (int h8 = 0; h8 < 2; h8++)
#pragma unroll
                    for (int j = 0; j < 2; j++) {
                        float e = __expf(sacc[mi][ni][h8 * 2 + j] - mn4[mi][h8]);
                        sacc[mi][ni][h8 * 2 + j] = e;
                        sl[mi][h8] += e;
                    }
#pragma unroll
        for (int mi = 0; mi < 2; mi++)
#pragma unroll
            for (int h8 = 0; h8 < 2; h8++) {
                sl[mi][h8] += __shfl_xor_sync(0xffffffffu, sl[mi][h8], 1);
                sl[mi][h8] += __shfl_xor_sync(0xffffffffu, sl[mi][h8], 2);
            }
        if ((lane & 3) == 0) {
#pragma unroll
            for (int mi = 0; mi < 2; mi++)
#pragma unroll
                for (int h8 = 0; h8 < 2; h8++)
                    reds[(wm * 32 + mi * 16 + r0 + h8 * 8) * 2 + wn] = sl[mi][h8];
        }
#pragma unroll
        for (int mi = 0; mi < 2; mi++)
#pragma unroll
            for (int ni = 0; ni < 10; ni++)
#pragma unroll
                for (int h8 = 0; h8 < 2; h8++) {
                    out[mi][ni][h8 * 2]     *= a4[mi][h8];
                    out[mi][ni][h8 * 2 + 1] *= a4[mi][h8];
                }
        __syncthreads();
        if (wn == 0) {
            int row = wm * 32 + lane;
            l_s[row] = l_s[row] * al_s[row] + reds[row * 2] + reds[row * 2 + 1];
        }

#pragma unroll
        for (int kk = 0; kk < 2; kk++) {
            uint32_t pa_h[2][4], pa_l[2][4];
            int tni = kk * 2;
#pragma unroll
            for (int mi = 0; mi < 2; mi++) {
                split2(sacc[mi][tni][0], sacc[mi][tni][1], pa_h[mi][0], pa_l[mi][0]);
                split2(sacc[mi][tni][2], sacc[mi][tni][3], pa_h[mi][1], pa_l[mi][1]);
                split2(sacc[mi][tni + 1][0], sacc[mi][tni + 1][1], pa_h[mi][2], pa_l[mi][2]);
                split2(sacc[mi][tni + 1][2], sacc[mi][tni + 1][3], pa_h[mi][3], pa_l[mi][3]);
            }
            uint32_t vbase = sb + 4 * ATT_TILE
                           + (wn * 32 + kk * 16 + (lane & 15)) * SVB + (lane >> 4) * 16;
#pragma unroll
            for (int nt = 0; nt < 5; nt++) {
                uint32_t rh[4], rl[4];
                ldx4t(rh, vbase + nt * 32);
                ldx4t(rl, vbase + ATT_TILE + nt * 32);
                uint32_t vbh0[2] = {rh[0], rh[1]}, vbh1[2] = {rh[2], rh[3]};
                uint32_t vbl0[2] = {rl[0], rl[1]}, vbl1[2] = {rl[2], rl[3]};
#pragma unroll
                for (int mi = 0; mi < 2; mi++) {
                    hmma(out[mi][nt * 2], pa_h[mi], vbh0);
                    hmma(out[mi][nt * 2], pa_h[mi], vbl0);
                    hmma(out[mi][nt * 2], pa_l[mi], vbh0);
                    hmma(out[mi][nt * 2 + 1], pa_h[mi], vbh1);
                    hmma(out[mi][nt * 2 + 1], pa_h[mi], vbl1);
                    hmma(out[mi][nt * 2 + 1], pa_l[mi], vbh1);
                }
            }
        }
    }

    __syncthreads();
    float* stage = (float*)smem;
    if (wn == 1) {
#pragma unroll
        for (int mi = 0; mi < 2; mi++)
#pragma unroll
            for (int ni = 0; ni < 10; ni++)
#pragma unroll
                for (int h8 = 0; h8 < 2; h8++) {
                    int row = wm * 32 + mi * 16 + r0 + h8 * 8;
                    int col = ni * 8 + c0;
                    stage[row * 84 + col] = out[mi][ni][h8 * 2];
                    stage[row * 84 + col + 1] = out[mi][ni][h8 * 2 + 1];
                }
    }
    __syncthreads();
    if (wn == 0) {
#pragma unroll
        for (int mi = 0; mi < 2; mi++)
#pragma unroll
            for (int h8 = 0; h8 < 2; h8++) {
                int row = wm * 32 + mi * 16 + r0 + h8 * 8;
                int srow = q0 + row;
                if (srow >= S_) continue;
                float rl = 1.f / l_s[row];
#pragma unroll
                for (int ni = 0; ni < 10; ni++) {
                    int col = ni * 8 + c0;
                    float vx = (out[mi][ni][h8 * 2] + stage[row * 84 + col]) * rl;
                    float vy = (out[mi][ni][h8 * 2 + 1] + stage[row * 84 + col + 1]) * rl;
                    uint32_t hi2, lo2;
                    split2(vx, vy, hi2, lo2);
                    size_t oidx = ((size_t)b * S_ + srow) * D_ + h * HD_ + col;
                    *(uint32_t*)&at_hi[oidx] = hi2;
                    *(uint32_t*)&at_lo[oidx] = lo2;
                }
            }
    }
}

// ----------------------------------------------------------------
extern "C" void kernel_launch(void* const* d_in, const int* in_sizes, int n_in,
                              void* d_out, int out_size)
{
    const float* hs = (const float*)d_in[0];
    const float* fc = (const float*)d_in[1];
    const float* fs = (const float*)d_in[2];
    const float* W[4] = { (const float*)d_in[3], (const float*)d_in[5],
                          (const float*)d_in[7], (const float*)d_in[9] };
    const float* bq = (const float*)d_in[4];
    const float* bk = (const float*)d_in[6];
    const float* bv = (const float*)d_in[8];
    const float* bo = (const float*)d_in[10];
    float* out = (float*)d_out;

    __nv_bfloat16 *hshi, *hslo, *whi, *wlo, *athi, *atlo;
    __nv_bfloat16 *qhi, *qlo, *khi, *klo, *vhi, *vlo;
    cudaGetSymbolAddress((void**)&hshi, g_hs_hi);
    cudaGetSymbolAddress((void**)&hslo, g_hs_lo);
    cudaGetSymbolAddress((void**)&whi, g_w_hi);
    cudaGetSymbolAddress((void**)&wlo, g_w_lo);
    cudaGetSymbolAddress((void**)&athi, g_at_hi);
    cudaGetSymbolAddress((void**)&atlo, g_at_lo);
    cudaGetSymbolAddress((void**)&qhi, g_qhi);
    cudaGetSymbolAddress((void**)&qlo, g_qlo);
    cudaGetSymbolAddress((void**)&khi, g_khi);
    cudaGetSymbolAddress((void**)&klo, g_klo);
    cudaGetSymbolAddress((void**)&vhi, g_vhi);
    cudaGetSymbolAddress((void**)&vlo, g_vlo);

    {
        int n = M_ * K_;
        split_kernel<<<(n + 255) / 256, 256>>>(hs, hshi, hslo, n);
        int nw = K_ * N_;
        for (int i = 0; i < 4; i++)
            split_kernel<<<(nw + 255) / 256, 256>>>(W[i], whi + (size_t)i * nw,
                                                    wlo + (size_t)i * nw, nw);
    }

    cudaFuncSetAttribute(gemm_hmma<0>, cudaFuncAttributeMaxDynamicSharedMemorySize,
                         GEMM_SMEM);
    cudaFuncSetAttribute(gemm_hmma<1>, cudaFuncAttributeMaxDynamicSharedMemorySize,
                         GEMM_SMEM);
    size_t wsz = (size_t)K_ * N_;

    // fused QKV: grid (30, 73); weights rows 0..3839 of whi/wlo
    gemm_hmma<1><<<dim3(30, (M_ + 127) / 128), 256, GEMM_SMEM>>>(
        hshi, hslo, whi, wlo, bq, bk, bv,
        nullptr, qhi, qlo, khi, klo, vhi, vlo, fc, fs, M_);

    cudaFuncSetAttribute(attn_hmma, cudaFuncAttributeMaxDynamicSharedMemorySize,
                         ATT_SMEM);
    attn_hmma<<<dim3(10, H_, B_), 128, ATT_SMEM>>>(qhi, qlo, khi, klo, vhi, vlo,
                                                   athi, atlo);

    // O projection
    gemm_hmma<0><<<dim3(10, (M_ + 127) / 128), 256, GEMM_SMEM>>>(
        athi, atlo, whi + 3 * wsz, wlo + 3 * wsz, bo, bo, bo,
        out, nullptr, nullptr, nullptr, nullptr, nullptr, nullptr, fc, fs, M_);
}

// round 6
// speedup vs baseline: 4.3305x; 1.2357x over previous
#include <cuda_runtime.h>
#include <cuda_bf16.h>
#include <cuda_fp16.h>
#include <math.h>
#include <stdint.h>

#define B_    16
#define S_    577
#define D_    1280
#define H_    16
#define HD_   80
#define HALF_ 40
#define M_    (B_*S_)   // 9232
#define K_    1280
#define N_    1280

// ---------------------------------------------------------------- scratch
__device__ __align__(16) __half g_hs_hi[M_*K_];
__device__ __align__(16) __half g_hs_lo[M_*K_];
__device__ __align__(16) __half g_w16[4*K_*N_];
__device__ __align__(16) __half g_at_hi[M_*K_];
__device__ __align__(16) __half g_at_lo[M_*K_];
__device__ __align__(16) __nv_bfloat16 g_qhi[B_*H_*S_*HD_];
__device__ __align__(16) __nv_bfloat16 g_qlo[B_*H_*S_*HD_];
__device__ __align__(16) __nv_bfloat16 g_khi[B_*H_*S_*HD_];
__device__ __align__(16) __nv_bfloat16 g_klo[B_*H_*S_*HD_];
__device__ __align__(16) __nv_bfloat16 g_vhi[B_*H_*S_*HD_];
__device__ __align__(16) __nv_bfloat16 g_vlo[B_*H_*S_*HD_];

// ---------------------------------------------------------------- helpers
__device__ __forceinline__ uint32_t smem_u32(const void* p) {
    uint32_t a;
    asm("{ .reg .u64 t; cvta.to.shared.u64 t, %1; cvt.u32.u64 %0, t; }"
        : "=r"(a) : "l"(p));
    return a;
}
__device__ __forceinline__ void cp16(uint32_t dst, const void* src, int sz) {
    asm volatile("cp.async.cg.shared.global [%0], [%1], 16, %2;"
                 :: "r"(dst), "l"(src), "r"(sz) : "memory");
}
#define CP_COMMIT() asm volatile("cp.async.commit_group;" ::: "memory")
#define CP_WAIT0()  asm volatile("cp.async.wait_group 0;" ::: "memory")

__device__ __forceinline__ void ldx4(uint32_t* r, uint32_t addr) {
    asm volatile("ldmatrix.sync.aligned.m8n8.x4.shared.b16 {%0,%1,%2,%3}, [%4];"
                 : "=r"(r[0]), "=r"(r[1]), "=r"(r[2]), "=r"(r[3]) : "r"(addr));
}
__device__ __forceinline__ void ldx4t(uint32_t* r, uint32_t addr) {
    asm volatile("ldmatrix.sync.aligned.m8n8.x4.trans.shared.b16 {%0,%1,%2,%3}, [%4];"
                 : "=r"(r[0]), "=r"(r[1]), "=r"(r[2]), "=r"(r[3]) : "r"(addr));
}
// bf16 HMMA (attention)
__device__ __forceinline__ void hmma(float* d, const uint32_t* a, const uint32_t* b) {
    asm volatile(
        "mma.sync.aligned.m16n8k16.row.col.f32.bf16.bf16.f32 "
        "{%0,%1,%2,%3}, {%4,%5,%6,%7}, {%8,%9}, {%0,%1,%2,%3};"
        : "+f"(d[0]), "+f"(d[1]), "+f"(d[2]), "+f"(d[3])
        : "r"(a[0]), "r"(a[1]), "r"(a[2]), "r"(a[3]), "r"(b[0]), "r"(b[1]));
}
// fp16 HMMA (projections)
__device__ __forceinline__ void hmma16(float* d, const uint32_t* a, const uint32_t* b) {
    asm volatile(
        "mma.sync.aligned.m16n8k16.row.col.f32.f16.f16.f32 "
        "{%0,%1,%2,%3}, {%4,%5,%6,%7}, {%8,%9}, {%0,%1,%2,%3};"
        : "+f"(d[0]), "+f"(d[1]), "+f"(d[2]), "+f"(d[3])
        : "r"(a[0]), "r"(a[1]), "r"(a[2]), "r"(a[3]), "r"(b[0]), "r"(b[1]));
}
__device__ __forceinline__ void split2(float x, float y, uint32_t& hi, uint32_t& lo) {
    __nv_bfloat162 h = __floats2bfloat162_rn(x, y);
    float hx = __bfloat162float(h.x), hy = __bfloat162float(h.y);
    __nv_bfloat162 l = __floats2bfloat162_rn(x - hx, y - hy);
    hi = *(uint32_t*)&h; lo = *(uint32_t*)&l;
}
__device__ __forceinline__ void split2h(float x, float y, uint32_t& hi, uint32_t& lo) {
    __half2 h = __floats2half2_rn(x, y);
    float hx = __half2float(h.x), hy = __half2float(h.y);
    __half2 l = __floats2half2_rn(x - hx, y - hy);
    hi = *(uint32_t*)&h; lo = *(uint32_t*)&l;
}

// ---------------------------------------------------------------- fp32 -> fp16 hi/lo split
__global__ __launch_bounds__(256)
void split_h_kernel(const float* __restrict__ x,
                    __half* __restrict__ hi, __half* __restrict__ lo, int n)
{
    int i = blockIdx.x * blockDim.x + threadIdx.x;
    if (i >= n) return;
    float v = x[i];
    __half h = __float2half_rn(v);
    hi[i] = h;
    lo[i] = __float2half_rn(v - __half2float(h));
}

// all 4 weight matrices -> fp16 in one launch
__global__ __launch_bounds__(256)
void w2h_kernel(const float* __restrict__ w0, const float* __restrict__ w1,
                const float* __restrict__ w2, const float* __restrict__ w3,
                __half* __restrict__ dst)
{
    const int nw = K_ * N_;
    int i = blockIdx.x * blockDim.x + threadIdx.x;
    if (i >= 4 * nw) return;
    int mat = i / nw, off = i - mat * nw;
    const float* src = (mat == 0) ? w0 : (mat == 1) ? w1 : (mat == 2) ? w2 : w3;
    dst[i] = __float2half_rn(src[off]);
}

// ---------------------------------------------------------------- fp16 HMMA GEMM (2-pass)
// C = (Ahi + Alo) * Bh^T + bias
// MODE 0: fp32 out [M,1280].  MODE 1: fused QKV (grid.x=30) epilogue rope/split.
#define SPADB 80                  // bytes per smem row (32 fp16 = 64B + 16 pad)
#define TILEB (128*SPADB)         // 10240
#define STAGEB (3*TILEB)          // Ahi, Alo, Bh = 30720
#define GEMM_SMEM (3*STAGEB)      // 3 stages = 92160
#define NIT (K_/32)               // 40

template<int MODE>
__global__ __launch_bounds__(256, 2)
void gemm_hmma(const __half* __restrict__ Ahi, const __half* __restrict__ Alo,
               const __half* __restrict__ Bh,
               const float* __restrict__ bq, const float* __restrict__ bk,
               const float* __restrict__ bv,
               float* __restrict__ Cf,
               __nv_bfloat16* __restrict__ qhi, __nv_bfloat16* __restrict__ qlo,
               __nv_bfloat16* __restrict__ khi, __nv_bfloat16* __restrict__ klo,
               __nv_bfloat16* __restrict__ vhi, __nv_bfloat16* __restrict__ vlo,
               const float* __restrict__ fc, const float* __restrict__ fs,
               int M)
{
    extern __shared__ __align__(16) char smem[];
    const int tid = threadIdx.x, wid = tid >> 5, lane = tid & 31;
    const int bn = blockIdx.x, bm = blockIdx.y;
    const int wm = wid >> 2, wn = wid & 3;
    const int row0A = bm * 128, row0B = bn * 128;
    const uint32_t sbase = smem_u32(smem);

    float acc[4][4][4];
#pragma unroll
    for (int i = 0; i < 4; i++)
#pragma unroll
        for (int j = 0; j < 4; j++)
#pragma unroll
            for (int c = 0; c < 4; c++) acc[i][j][c] = 0.f;

    // 1536 cp16 units per stage = 6 per thread
    auto load_stage = [&](int st, int k0) {
        uint32_t sdst = sbase + st * STAGEB;
#pragma unroll
        for (int t = 0; t < 6; t++) {
            int idx = tid + t * 256;          // 0..1535
            int tile = idx >> 9;              // 0=Ahi,1=Alo,2=Bh
            int w = idx & 511;
            int r = w >> 2, seg = w & 3;
            uint32_t d = sdst + tile * TILEB + r * SPADB + seg * 16;
            const __half* sp;
            int sz = 16;
            if (tile < 2) {
                int row = row0A + r;
                if (row >= M) { row = M - 1; sz = 0; }
                sp = (tile == 0 ? Ahi : Alo) + (size_t)row * K_ + k0 + seg * 8;
            } else {
                int row = row0B + r;
                sp = Bh + (size_t)row * K_ + k0 + seg * 8;
            }
            cp16(d, sp, sz);
        }
        CP_COMMIT();
    };

    const uint32_t a_lane = (uint32_t)((wm * 64 + (lane & 15)) * SPADB + (lane >> 4) * 16);
    const uint32_t b_lane = (uint32_t)((wn * 32 + ((lane >> 4) << 3) + (lane & 7)) * SPADB
                                       + ((lane >> 3) & 1) * 16);

    load_stage(0, 0);
    load_stage(1, 32);

    for (int it = 0; it < NIT; it++) {
        int cur = it % 3;
        if (it + 2 < NIT) load_stage((it + 2) % 3, (it + 2) * 32);
        if (it + 2 < NIT)      { asm volatile("cp.async.wait_group 2;" ::: "memory"); }
        else if (it + 1 < NIT) { asm volatile("cp.async.wait_group 1;" ::: "memory"); }
        else                   { CP_WAIT0(); }
        __syncthreads();

        uint32_t scur = sbase + cur * STAGEB;
#pragma unroll
        for (int kk = 0; kk < 2; kk++) {
            uint32_t ab = scur + a_lane + kk * 32;
            uint32_t bb = scur + 2 * TILEB + b_lane + kk * 32;

            uint32_t af[4][4], bf[4][2];
#pragma unroll
            for (int mi = 0; mi < 4; mi++) ldx4(af[mi], ab + mi * 16 * SPADB);
#pragma unroll
            for (int np = 0; np < 2; np++) {
                uint32_t r[4];
                ldx4(r, bb + np * 16 * SPADB);
                bf[np * 2][0] = r[0]; bf[np * 2][1] = r[1];
                bf[np * 2 + 1][0] = r[2]; bf[np * 2 + 1][1] = r[3];
            }
            // pass 1: Ahi * Bh
#pragma unroll
            for (int mi = 0; mi < 4; mi++)
#pragma unroll
                for (int ni = 0; ni < 4; ni++) hmma16(acc[mi][ni], af[mi], bf[ni]);
            // pass 2: Alo * Bh
#pragma unroll
            for (int mi = 0; mi < 4; mi++) ldx4(af[mi], ab + TILEB + mi * 16 * SPADB);
#pragma unroll
            for (int mi = 0; mi < 4; mi++)
#pragma unroll
                for (int ni = 0; ni < 4; ni++) hmma16(acc[mi][ni], af[mi], bf[ni]);
        }
        __syncthreads();
    }

    // ---- epilogue ----
    const int mrow = (lane >> 2);
    const int ncol = (lane & 3) * 2;

    const float rscale = 0.11180339887498949f;  // 1/sqrt(80)
    const float* bias = bq;
    __nv_bfloat16 *Chi = qhi, *Clo = qlo;
    float scale = 1.f;
    bool dorope = false;
    if (MODE == 1) {
        int mat = bn / 10;
        bias = (mat == 0) ? bq : (mat == 1) ? bk : bv;
        Chi = (mat == 0) ? qhi : (mat == 1) ? khi : vhi;
        Clo = (mat == 0) ? qlo : (mat == 1) ? klo : vlo;
        scale = (mat == 0) ? rscale : 1.f;
        dorope = (mat < 2);
    }
    const int nbase = (MODE == 1) ? (bn % 10) * 128 : bn * 128;

#pragma unroll
    for (int mi = 0; mi < 4; mi++) {
#pragma unroll
        for (int h2 = 0; h2 < 2; h2++) {
            int m = row0A + wm * 64 + mi * 16 + mrow + h2 * 8;
            if (m >= M) continue;
            int bb2 = m / S_, ss = m - bb2 * S_;
#pragma unroll
            for (int ni = 0; ni < 4; ni++) {
                int n0 = nbase + wn * 32 + ni * 8 + ncol;
                float vx = acc[mi][ni][h2 * 2] + bias[n0];
                float vy = acc[mi][ni][h2 * 2 + 1] + bias[n0 + 1];
                if (MODE == 0) {
                    float2 v = make_float2(vx, vy);
                    *(float2*)&Cf[(size_t)m * N_ + n0] = v;
                } else {
                    int h = n0 / HD_, d = n0 - h * HD_;
                    float rx = vx, ry = vy;
                    if (dorope) {
                        int j = d >> 1;
                        float c = fc[ss * HALF_ + j], sn = fs[ss * HALF_ + j];
                        rx = (vx * c - vy * sn) * scale;
                        ry = (vx * sn + vy * c) * scale;
                    }
                    uint32_t hi2, lo2;
                    split2(rx, ry, hi2, lo2);
                    size_t idx = ((size_t)(bb2 * H_ + h) * S_ + ss) * HD_ + d;
                    *(uint32_t*)&Chi[idx] = hi2;
                    *(uint32_t*)&Clo[idx] = lo2;
                }
            }
        }
    }
}

// ---------------------------------------------------------------- HMMA flash attention (bf16 3-pass)
#define SVB 176                   // bytes per smem row (80 bf16 + 8 pad)
#define ATT_TILE (64*SVB)         // 11264
#define ATT_SMEM (6*ATT_TILE + 64*4*3 + 128*4*2)

__global__ __launch_bounds__(128)
void attn_hmma(const __nv_bfloat16* __restrict__ qhi, const __nv_bfloat16* __restrict__ qlo,
               const __nv_bfloat16* __restrict__ khi, const __nv_bfloat16* __restrict__ klo,
               const __nv_bfloat16* __restrict__ vhi, const __nv_bfloat16* __restrict__ vlo,
               __half* __restrict__ at_hi, __half* __restrict__ at_lo)
{
    extern __shared__ __align__(16) char smem[];
    const uint32_t sb = smem_u32(smem);
    float* m_s  = (float*)(smem + 6 * ATT_TILE);
    float* l_s  = m_s + 64;
    float* al_s = l_s + 64;
    float* redm = al_s + 64;
    float* reds = redm + 128;

    const int tid = threadIdx.x, wid = tid >> 5, lane = tid & 31;
    const int wm = wid >> 1, wn = wid & 1;
    const int qt = blockIdx.x, h = blockIdx.y, b = blockIdx.z;
    const int bh = b * H_ + h;
    const size_t off = (size_t)bh * S_ * HD_;
    const int q0 = qt * 64;

#pragma unroll
    for (int t = 0; t < 10; t++) {
        int i = tid + t * 128;
        int tile = i / 640;
        int rr = (i % 640) / 10, seg = i % 10;
        int row = q0 + rr;
        int sz = (row < S_) ? 16 : 0;
        if (row >= S_) row = S_ - 1;
        const __nv_bfloat16* sp = (tile ? qlo : qhi) + off + (size_t)row * HD_ + seg * 8;
        cp16(sb + tile * ATT_TILE + rr * SVB + seg * 16, sp, sz);
    }
    CP_COMMIT();

    if (tid < 64) { m_s[tid] = -1e30f; l_s[tid] = 0.f; }

    float out[2][10][4];
#pragma unroll
    for (int mi = 0; mi < 2; mi++)
#pragma unroll
        for (int ni = 0; ni < 10; ni++)
#pragma unroll
            for (int c = 0; c < 4; c++) out[mi][ni][c] = 0.f;

    const int r0 = lane >> 2, c0 = (lane & 3) * 2;

    for (int kt = 0; kt < 10; kt++) {
        __syncthreads();
#pragma unroll
        for (int t = 0; t < 20; t++) {
            int i = tid + t * 128;
            int tile = i / 640;
            int rr = (i % 640) / 10, seg = i % 10;
            int row = kt * 64 + rr;
            int sz = (row < S_) ? 16 : 0;
            if (row >= S_) row = S_ - 1;
            const __nv_bfloat16* sp =
                (tile == 0 ? khi : tile == 1 ? klo : tile == 2 ? vhi : vlo)
                + off + (size_t)row * HD_ + seg * 8;
            cp16(sb + (2 + tile) * ATT_TILE + rr * SVB + seg * 16, sp, sz);
        }
        CP_COMMIT();
        CP_WAIT0();
        __syncthreads();

        float sacc[2][4][4];
#pragma unroll
        for (int mi = 0; mi < 2; mi++)
#pragma unroll
            for (int ni = 0; ni < 4; ni++)
#pragma unroll
                for (int c = 0; c < 4; c++) sacc[mi][ni][c] = 0.f;

#pragma unroll
        for (int k16 = 0; k16 < 5; k16++) {
            uint32_t ah[2][4], al[2][4], bh2[4][2], bl2[4][2];
            uint32_t abase = sb + (wm * 32 + (lane & 15)) * SVB + (lane >> 4) * 16 + k16 * 32;
#pragma unroll
            for (int mi = 0; mi < 2; mi++) {
                ldx4(ah[mi], abase + mi * 16 * SVB);
                ldx4(al[mi], abase + ATT_TILE + mi * 16 * SVB);
            }
            uint32_t bbase = sb + 2 * ATT_TILE
                           + (wn * 32 + ((lane >> 4) << 3) + (lane & 7)) * SVB
                           + ((lane >> 3) & 1) * 16 + k16 * 32;
#pragma unroll
            for (int nt = 0; nt < 2; nt++) {
                uint32_t r[4];
                ldx4(r, bbase + nt * 16 * SVB);
                bh2[nt * 2][0] = r[0]; bh2[nt * 2][1] = r[1];
                bh2[nt * 2 + 1][0] = r[2]; bh2[nt * 2 + 1][1] = r[3];
                ldx4(r, bbase + ATT_TILE + nt * 16 * SVB);
                bl2[nt * 2][0] = r[0]; bl2[nt * 2][1] = r[1];
                bl2[nt * 2 + 1][0] = r[2]; bl2[nt * 2 + 1][1] = r[3];
            }
#pragma unroll
            for (int mi = 0; mi < 2; mi++)
#pragma unroll
                for (int ni = 0; ni < 4; ni++) {
                    hmma(sacc[mi][ni], ah[mi], bh2[ni]);
                    hmma(sacc[mi][ni], ah[mi], bl2[ni]);
                    hmma(sacc[mi][ni], al[mi], bh2[ni]);
                }
        }

        float mloc[2][2] = {{-1e30f, -1e30f}, {-1e30f, -1e30f}};
#pragma unroll
        for (int mi = 0; mi < 2; mi++)
#pragma unroll
            for (int ni = 0; ni < 4; ni++)
#pragma unroll
                for (int h8 = 0; h8 < 2; h8++)
#pragma unroll
                    for (int j = 0; j < 2; j++) {
                        int key = kt * 64 + wn * 32 + ni * 8 + c0 + j;
                        float sv = (key < S_) ? sacc[mi][ni][h8 * 2 + j] : -1e30f;
                        sacc[mi][ni][h8 * 2 + j] = sv;
                        mloc[mi][h8] = fmaxf(mloc[mi][h8], sv);
                    }
#pragma unroll
        for (int mi = 0; mi < 2; mi++)
#pragma unroll
            for (int h8 = 0; h8 < 2; h8++) {
                mloc[mi][h8] = fmaxf(mloc[mi][h8], __shfl_xor_sync(0xffffffffu, mloc[mi][h8], 1));
                mloc[mi][h8] = fmaxf(mloc[mi][h8], __shfl_xor_sync(0xffffffffu, mloc[mi][h8], 2));
            }
        if ((lane & 3) == 0) {
#pragma unroll
            for (int mi = 0; mi < 2; mi++)
#pragma unroll
                for (int h8 = 0; h8 < 2; h8++)
                    redm[(wm * 32 + mi * 16 + r0 + h8 * 8) * 2 + wn] = mloc[mi][h8];
        }
        __syncthreads();
        if (wn == 0) {
            int row = wm * 32 + lane;
            float mn = fmaxf(fmaxf(redm[row * 2], redm[row * 2 + 1]), m_s[row]);
            al_s[row] = __expf(m_s[row] - mn);
            m_s[row] = mn;
        }
        __syncthreads();

        float mn4[2][2], a4[2][2];
#pragma unroll
        for (int mi = 0; mi < 2; mi++)
#pragma unroll
            for (int h8 = 0; h8 < 2; h8++) {
                int row = wm * 32 + mi * 16 + r0 + h8 * 8;
                mn4[mi][h8] = m_s[row];
                a4[mi][h8] = al_s[row];
            }
        float sl[2][2] = {{0.f, 0.f}, {0.f, 0.f}};
#pragma unroll
        for (int mi = 0; mi < 2; mi++)
#pragma unroll
            for (int ni = 0; ni < 4; ni++)
#pragma unroll
                for (int h8 = 0; h8 < 2; h8++)
#pragma unroll
                    for (int j = 0; j < 2; j++) {
                        float e = __expf(sacc[mi][ni][h8 * 2 + j] - mn4[mi][h8]);
                        sacc[mi][ni][h8 * 2 + j] = e;
                        sl[mi][h8] += e;
                    }
#pragma unroll
        for (int mi = 0; mi < 2; mi++)
#pragma unroll
            for (int h8 = 0; h8 < 2; h8++) {
                sl[mi][h8] += __shfl_xor_sync(0xffffffffu, sl[mi][h8], 1);
                sl[mi][h8] += __shfl_xor_sync(0xffffffffu, sl[mi][h8], 2);
            }
        if ((lane & 3) == 0) {
#pragma unroll
            for (int mi = 0; mi < 2; mi++)
#pragma unroll
                for (int h8 = 0; h8 < 2; h8++)
                    reds[(wm * 32 + mi * 16 + r0 + h8 * 8) * 2 + wn] = sl[mi][h8];
        }
#pragma unroll
        for (int mi = 0; mi < 2; mi++)
#pragma unroll
            for (int ni = 0; ni < 10; ni++)
#pragma unroll
                for (int h8 = 0; h8 < 2; h8++) {
                    out[mi][ni][h8 * 2]     *= a4[mi][h8];
                    out[mi][ni][h8 * 2 + 1] *= a4[mi][h8];
                }
        __syncthreads();
        if (wn == 0) {
            int row = wm * 32 + lane;
            l_s[row] = l_s[row] * al_s[row] + reds[row * 2] + reds[row * 2 + 1];
        }

#pragma unroll
        for (int kk = 0; kk < 2; kk++) {
            uint32_t pa_h[2][4], pa_l[2][4];
            int tni = kk * 2;
#pragma unroll
            for (int mi = 0; mi < 2; mi++) {
                split2(sacc[mi][tni][0], sacc[mi][tni][1], pa_h[mi][0], pa_l[mi][0]);
                split2(sacc[mi][tni][2], sacc[mi][tni][3], pa_h[mi][1], pa_l[mi][1]);
                split2(sacc[mi][tni + 1][0], sacc[mi][tni + 1][1], pa_h[mi][2], pa_l[mi][2]);
                split2(sacc[mi][tni + 1][2], sacc[mi][tni + 1][3], pa_h[mi][3], pa_l[mi][3]);
            }
            uint32_t vbase = sb + 4 * ATT_TILE
                           + (wn * 32 + kk * 16 + (lane & 15)) * SVB + (lane >> 4) * 16;
#pragma unroll
            for (int nt = 0; nt < 5; nt++) {
                uint32_t rh[4], rl[4];
                ldx4t(rh, vbase + nt * 32);
                ldx4t(rl, vbase + ATT_TILE + nt * 32);
                uint32_t vbh0[2] = {rh[0], rh[1]}, vbh1[2] = {rh[2], rh[3]};
                uint32_t vbl0[2] = {rl[0], rl[1]}, vbl1[2] = {rl[2], rl[3]};
#pragma unroll
                for (int mi = 0; mi < 2; mi++) {
                    hmma(out[mi][nt * 2], pa_h[mi], vbh0);
                    hmma(out[mi][nt * 2], pa_h[mi], vbl0);
                    hmma(out[mi][nt * 2], pa_l[mi], vbh0);
                    hmma(out[mi][nt * 2 + 1], pa_h[mi], vbh1);
                    hmma(out[mi][nt * 2 + 1], pa_h[mi], vbl1);
                    hmma(out[mi][nt * 2 + 1], pa_l[mi], vbh1);
                }
            }
        }
    }

    __syncthreads();
    float* stage = (float*)smem;
    if (wn == 1) {
#pragma unroll
        for (int mi = 0; mi < 2; mi++)
#pragma unroll
            for (int ni = 0; ni < 10; ni++)
#pragma unroll
                for (int h8 = 0; h8 < 2; h8++) {
                    int row = wm * 32 + mi * 16 + r0 + h8 * 8;
                    int col = ni * 8 + c0;
                    stage[row * 84 + col] = out[mi][ni][h8 * 2];
                    stage[row * 84 + col + 1] = out[mi][ni][h8 * 2 + 1];
                }
    }
    __syncthreads();
    if (wn == 0) {
#pragma unroll
        for (int mi = 0; mi < 2; mi++)
#pragma unroll
            for (int h8 = 0; h8 < 2; h8++) {
                int row = wm * 32 + mi * 16 + r0 + h8 * 8;
                int srow = q0 + row;
                if (srow >= S_) continue;
                float rl = 1.f / l_s[row];
#pragma unroll
                for (int ni = 0; ni < 10; ni++) {
                    int col = ni * 8 + c0;
                    float vx = (out[mi][ni][h8 * 2] + stage[row * 84 + col]) * rl;
                    float vy = (out[mi][ni][h8 * 2 + 1] + stage[row * 84 + col + 1]) * rl;
                    uint32_t hi2, lo2;
                    split2h(vx, vy, hi2, lo2);
                    size_t oidx = ((size_t)b * S_ + srow) * D_ + h * HD_ + col;
                    *(uint32_t*)&at_hi[oidx] = hi2;
                    *(uint32_t*)&at_lo[oidx] = lo2;
                }
            }
    }
}

// ----------------------------------------------------------------
extern "C" void kernel_launch(void* const* d_in, const int* in_sizes, int n_in,
                              void* d_out, int out_size)
{
    const float* hs = (const float*)d_in[0];
    const float* fc = (const float*)d_in[1];
    const float* fs = (const float*)d_in[2];
    const float* Wq = (const float*)d_in[3];
    const float* bq = (const float*)d_in[4];
    const float* Wk = (const float*)d_in[5];
    const float* bk = (const float*)d_in[6];
    const float* Wv = (const float*)d_in[7];
    const float* bv = (const float*)d_in[8];
    const float* Wo = (const float*)d_in[9];
    const float* bo = (const float*)d_in[10];
    float* out = (float*)d_out;

    __half *hshi, *hslo, *w16, *athi, *atlo;
    __nv_bfloat16 *qhi, *qlo, *khi, *klo, *vhi, *vlo;
    cudaGetSymbolAddress((void**)&hshi, g_hs_hi);
    cudaGetSymbolAddress((void**)&hslo, g_hs_lo);
    cudaGetSymbolAddress((void**)&w16, g_w16);
    cudaGetSymbolAddress((void**)&athi, g_at_hi);
    cudaGetSymbolAddress((void**)&atlo, g_at_lo);
    cudaGetSymbolAddress((void**)&qhi, g_qhi);
    cudaGetSymbolAddress((void**)&qlo, g_qlo);
    cudaGetSymbolAddress((void**)&khi, g_khi);
    cudaGetSymbolAddress((void**)&klo, g_klo);
    cudaGetSymbolAddress((void**)&vhi, g_vhi);
    cudaGetSymbolAddress((void**)&vlo, g_vlo);

    {
        int n = M_ * K_;
        split_h_kernel<<<(n + 255) / 256, 256>>>(hs, hshi, hslo, n);
        int nw4 = 4 * K_ * N_;
        w2h_kernel<<<(nw4 + 255) / 256, 256>>>(Wq, Wk, Wv, Wo, w16);
    }

    cudaFuncSetAttribute(gemm_hmma<0>, cudaFuncAttributeMaxDynamicSharedMemorySize,
                         GEMM_SMEM);
    cudaFuncSetAttribute(gemm_hmma<1>, cudaFuncAttributeMaxDynamicSharedMemorySize,
                         GEMM_SMEM);
    size_t wsz = (size_t)K_ * N_;

    // fused QKV: grid (30, 73)
    gemm_hmma<1><<<dim3(30, (M_ + 127) / 128), 256, GEMM_SMEM>>>(
        hshi, hslo, w16, bq, bk, bv,
        nullptr, qhi, qlo, khi, klo, vhi, vlo, fc, fs, M_);

    cudaFuncSetAttribute(attn_hmma, cudaFuncAttributeMaxDynamicSharedMemorySize,
                         ATT_SMEM);
    attn_hmma<<<dim3(10, H_, B_), 128, ATT_SMEM>>>(qhi, qlo, khi, klo, vhi, vlo,
                                                   athi, atlo);

    // O projection
    gemm_hmma<0><<<dim3(10, (M_ + 127) / 128), 256, GEMM_SMEM>>>(
        athi, atlo, w16 + 3 * wsz, bo, bo, bo,
        out, nullptr, nullptr, nullptr, nullptr, nullptr, nullptr, fc, fs, M_);
}

// round 8
// speedup vs baseline: 4.7407x; 1.0947x over previous
#include <cuda_runtime.h>
#include <cuda_bf16.h>
#include <cuda_fp16.h>
#include <math.h>
#include <stdint.h>

#define B_    16
#define S_    577
#define D_    1280
#define H_    16
#define HD_   80
#define HALF_ 40
#define M_    (B_*S_)   // 9232
#define K_    1280
#define N_    1280

// ---------------------------------------------------------------- scratch
__device__ __align__(16) __half g_hs_hi[M_*K_];
__device__ __align__(16) __half g_hs_lo[M_*K_];
__device__ __align__(16) __half g_w16[4*K_*N_];
__device__ __align__(16) __half g_at_hi[M_*K_];
__device__ __align__(16) __half g_at_lo[M_*K_];
__device__ __align__(16) __half g_q16hi[B_*H_*S_*HD_];
__device__ __align__(16) __half g_q16lo[B_*H_*S_*HD_];
__device__ __align__(16) __half g_k16[B_*H_*S_*HD_];
__device__ __align__(16) __half g_v16[B_*H_*S_*HD_];

// ---------------------------------------------------------------- helpers
__device__ __forceinline__ uint32_t smem_u32(const void* p) {
    uint32_t a;
    asm("{ .reg .u64 t; cvta.to.shared.u64 t, %1; cvt.u32.u64 %0, t; }"
        : "=r"(a) : "l"(p));
    return a;
}
__device__ __forceinline__ void cp16(uint32_t dst, const void* src, int sz) {
    asm volatile("cp.async.cg.shared.global [%0], [%1], 16, %2;"
                 :: "r"(dst), "l"(src), "r"(sz) : "memory");
}
#define CP_COMMIT() asm volatile("cp.async.commit_group;" ::: "memory")
#define CP_WAIT0()  asm volatile("cp.async.wait_group 0;" ::: "memory")

__device__ __forceinline__ void ldx4(uint32_t* r, uint32_t addr) {
    asm volatile("ldmatrix.sync.aligned.m8n8.x4.shared.b16 {%0,%1,%2,%3}, [%4];"
                 : "=r"(r[0]), "=r"(r[1]), "=r"(r[2]), "=r"(r[3]) : "r"(addr));
}
__device__ __forceinline__ void ldx4t(uint32_t* r, uint32_t addr) {
    asm volatile("ldmatrix.sync.aligned.m8n8.x4.trans.shared.b16 {%0,%1,%2,%3}, [%4];"
                 : "=r"(r[0]), "=r"(r[1]), "=r"(r[2]), "=r"(r[3]) : "r"(addr));
}
__device__ __forceinline__ void hmma16(float* d, const uint32_t* a, const uint32_t* b) {
    asm volatile(
        "mma.sync.aligned.m16n8k16.row.col.f32.f16.f16.f32 "
        "{%0,%1,%2,%3}, {%4,%5,%6,%7}, {%8,%9}, {%0,%1,%2,%3};"
        : "+f"(d[0]), "+f"(d[1]), "+f"(d[2]), "+f"(d[3])
        : "r"(a[0]), "r"(a[1]), "r"(a[2]), "r"(a[3]), "r"(b[0]), "r"(b[1]));
}
__device__ __forceinline__ void split2h(float x, float y, uint32_t& hi, uint32_t& lo) {
    __half2 h = __floats2half2_rn(x, y);
    float hx = __half2float(h.x), hy = __half2float(h.y);
    __half2 l = __floats2half2_rn(x - hx, y - hy);
    hi = *(uint32_t*)&h; lo = *(uint32_t*)&l;
}

// ---------------------------------------------------------------- fp32 -> fp16 hi/lo split
__global__ __launch_bounds__(256)
void split_h_kernel(const float* __restrict__ x,
                    __half* __restrict__ hi, __half* __restrict__ lo, int n)
{
    int i = blockIdx.x * blockDim.x + threadIdx.x;
    if (i >= n) return;
    float v = x[i];
    __half h = __float2half_rn(v);
    hi[i] = h;
    lo[i] = __float2half_rn(v - __half2float(h));
}

__global__ __launch_bounds__(256)
void w2h_kernel(const float* __restrict__ w0, const float* __restrict__ w1,
                const float* __restrict__ w2, const float* __restrict__ w3,
                __half* __restrict__ dst)
{
    const int nw = K_ * N_;
    int i = blockIdx.x * blockDim.x + threadIdx.x;
    if (i >= 4 * nw) return;
    int mat = i / nw, off = i - mat * nw;
    const float* src = (mat == 0) ? w0 : (mat == 1) ? w1 : (mat == 2) ? w2 : w3;
    dst[i] = __float2half_rn(src[off]);
}

// ---------------------------------------------------------------- fp16 HMMA GEMM (2-pass)
#define SPADB 80
#define TILEB (128*SPADB)
#define STAGEB (3*TILEB)
#define GEMM_SMEM (3*STAGEB)
#define NIT (K_/32)

template<int MODE>
__global__ __launch_bounds__(256, 2)
void gemm_hmma(const __half* __restrict__ Ahi, const __half* __restrict__ Alo,
               const __half* __restrict__ Bh,
               const float* __restrict__ bq, const float* __restrict__ bk,
               const float* __restrict__ bv,
               float* __restrict__ Cf,
               __half* __restrict__ qhi, __half* __restrict__ qlo,
               __half* __restrict__ k16, __half* __restrict__ v16,
               const float* __restrict__ fc, const float* __restrict__ fs,
               int M)
{
    extern __shared__ __align__(16) char smem[];
    const int tid = threadIdx.x, wid = tid >> 5, lane = tid & 31;
    const int bn = blockIdx.x, bm = blockIdx.y;
    const int wm = wid >> 2, wn = wid & 3;
    const int row0A = bm * 128, row0B = bn * 128;
    const uint32_t sbase = smem_u32(smem);

    float acc[4][4][4];
#pragma unroll
    for (int i = 0; i < 4; i++)
#pragma unroll
        for (int j = 0; j < 4; j++)
#pragma unroll
            for (int c = 0; c < 4; c++) acc[i][j][c] = 0.f;

    auto load_stage = [&](int st, int k0) {
        uint32_t sdst = sbase + st * STAGEB;
#pragma unroll
        for (int t = 0; t < 6; t++) {
            int idx = tid + t * 256;
            int tile = idx >> 9;
            int w = idx & 511;
            int r = w >> 2, seg = w & 3;
            uint32_t d = sdst + tile * TILEB + r * SPADB + seg * 16;
            const __half* sp;
            int sz = 16;
            if (tile < 2) {
                int row = row0A + r;
                if (row >= M) { row = M - 1; sz = 0; }
                sp = (tile == 0 ? Ahi : Alo) + (size_t)row * K_ + k0 + seg * 8;
            } else {
                int row = row0B + r;
                sp = Bh + (size_t)row * K_ + k0 + seg * 8;
            }
            cp16(d, sp, sz);
        }
        CP_COMMIT();
    };

    const uint32_t a_lane = (uint32_t)((wm * 64 + (lane & 15)) * SPADB + (lane >> 4) * 16);
    const uint32_t b_lane = (uint32_t)((wn * 32 + ((lane >> 4) << 3) + (lane & 7)) * SPADB
                                       + ((lane >> 3) & 1) * 16);

    load_stage(0, 0);
    load_stage(1, 32);

    for (int it = 0; it < NIT; it++) {
        int cur = it % 3;
        if (it + 2 < NIT) load_stage((it + 2) % 3, (it + 2) * 32);
        if (it + 2 < NIT)      { asm volatile("cp.async.wait_group 2;" ::: "memory"); }
        else if (it + 1 < NIT) { asm volatile("cp.async.wait_group 1;" ::: "memory"); }
        else                   { CP_WAIT0(); }
        __syncthreads();

        uint32_t scur = sbase + cur * STAGEB;
#pragma unroll
        for (int kk = 0; kk < 2; kk++) {
            uint32_t ab = scur + a_lane + kk * 32;
            uint32_t bb = scur + 2 * TILEB + b_lane + kk * 32;

            uint32_t af[4][4], bf[4][2];
#pragma unroll
            for (int mi = 0; mi < 4; mi++) ldx4(af[mi], ab + mi * 16 * SPADB);
#pragma unroll
            for (int np = 0; np < 2; np++) {
                uint32_t r[4];
                ldx4(r, bb + np * 16 * SPADB);
                bf[np * 2][0] = r[0]; bf[np * 2][1] = r[1];
                bf[np * 2 + 1][0] = r[2]; bf[np * 2 + 1][1] = r[3];
            }
#pragma unroll
            for (int mi = 0; mi < 4; mi++)
#pragma unroll
                for (int ni = 0; ni < 4; ni++) hmma16(acc[mi][ni], af[mi], bf[ni]);
#pragma unroll
            for (int mi = 0; mi < 4; mi++) ldx4(af[mi], ab + TILEB + mi * 16 * SPADB);
#pragma unroll
            for (int mi = 0; mi < 4; mi++)
#pragma unroll
                for (int ni = 0; ni < 4; ni++) hmma16(acc[mi][ni], af[mi], bf[ni]);
        }
        __syncthreads();
    }

    // ---- epilogue ----
    const int mrow = (lane >> 2);
    const int ncol = (lane & 3) * 2;
    const float rscale = 0.11180339887498949f;  // 1/sqrt(80)

    int mat = 0;
    const float* bias = bq;
    if (MODE == 1) {
        mat = bn / 10;
        bias = (mat == 0) ? bq : (mat == 1) ? bk : bv;
    }
    const int nbase = (MODE == 1) ? (bn % 10) * 128 : bn * 128;

#pragma unroll
    for (int mi = 0; mi < 4; mi++) {
#pragma unroll
        for (int h2 = 0; h2 < 2; h2++) {
            int m = row0A + wm * 64 + mi * 16 + mrow + h2 * 8;
            if (m >= M) continue;
            int bb2 = m / S_, ss = m - bb2 * S_;
#pragma unroll
            for (int ni = 0; ni < 4; ni++) {
                int n0 = nbase + wn * 32 + ni * 8 + ncol;
                float vx = acc[mi][ni][h2 * 2] + bias[n0];
                float vy = acc[mi][ni][h2 * 2 + 1] + bias[n0 + 1];
                if (MODE == 0) {
                    float2 v = make_float2(vx, vy);
                    *(float2*)&Cf[(size_t)m * N_ + n0] = v;
                } else {
                    int h = n0 / HD_, d = n0 - h * HD_;
                    size_t idx = ((size_t)(bb2 * H_ + h) * S_ + ss) * HD_ + d;
                    if (mat == 0) {            // q: rope + scale + hi/lo split
                        int j = d >> 1;
                        float c = fc[ss * HALF_ + j], sn = fs[ss * HALF_ + j];
                        float rx = (vx * c - vy * sn) * rscale;
                        float ry = (vx * sn + vy * c) * rscale;
                        uint32_t hi2, lo2;
                        split2h(rx, ry, hi2, lo2);
                        *(uint32_t*)&qhi[idx] = hi2;
                        *(uint32_t*)&qlo[idx] = lo2;
                    } else if (mat == 1) {     // k: rope, single fp16
                        int j = d >> 1;
                        float c = fc[ss * HALF_ + j], sn = fs[ss * HALF_ + j];
                        float rx = vx * c - vy * sn;
                        float ry = vx * sn + vy * c;
                        __half2 hv = __floats2half2_rn(rx, ry);
                        *(__half2*)&k16[idx] = hv;
                    } else {                   // v: single fp16
                        __half2 hv = __floats2half2_rn(vx, vy);
                        *(__half2*)&v16[idx] = hv;
                    }
                }
            }
        }
    }
}

// ---------------------------------------------------------------- fp16 HMMA flash attention
// 256 threads = 8 warps: wm in 0..3 (16 q-rows each), wn in 0..1 (32-key split).
// QK = Qhi*K + Qlo*K (2 passes); PV = Phi*V + Plo*V (P split in-register).
#define SVB 176                   // 80 fp16 = 160B + 16 pad
#define ATT_TILE (64*SVB)         // 11264
#define ATT_SMEM (4*ATT_TILE + 64*4*3 + 128*4*2)

__global__ __launch_bounds__(256, 2)
void attn_hmma(const __half* __restrict__ qhi, const __half* __restrict__ qlo,
               const __half* __restrict__ k16, const __half* __restrict__ v16,
               __half* __restrict__ at_hi, __half* __restrict__ at_lo)
{
    extern __shared__ __align__(16) char smem[];
    const uint32_t sb = smem_u32(smem);
    float* m_s  = (float*)(smem + 4 * ATT_TILE);
    float* l_s  = m_s + 64;
    float* al_s = l_s + 64;
    float* redm = al_s + 64;   // [64][2]
    float* reds = redm + 128;  // [64][2]

    const int tid = threadIdx.x, wid = tid >> 5, lane = tid & 31;
    const int wm = wid >> 1, wn = wid & 1;
    const int qt = blockIdx.x, h = blockIdx.y, b = blockIdx.z;
    const int bh = b * H_ + h;
    const size_t off = (size_t)bh * S_ * HD_;
    const int q0 = qt * 64;

    // ---- load Q hi/lo (tiles 0,1) ----
#pragma unroll
    for (int t = 0; t < 5; t++) {
        int i = tid + t * 256;            // 0..1279
        int tile = i / 640;               // 0=Qhi,1=Qlo
        int rr = (i % 640) / 10, seg = i % 10;
        int row = q0 + rr;
        int sz = (row < S_) ? 16 : 0;
        if (row >= S_) row = S_ - 1;
        const __half* sp = (tile ? qlo : qhi) + off + (size_t)row * HD_ + seg * 8;
        cp16(sb + tile * ATT_TILE + rr * SVB + seg * 16, sp, sz);
    }
    CP_COMMIT();

    if (tid < 64) { m_s[tid] = -1e30f; l_s[tid] = 0.f; }

    float out[10][4];
#pragma unroll
    for (int ni = 0; ni < 10; ni++)
#pragma unroll
        for (int c = 0; c < 4; c++) out[ni][c] = 0.f;

    const int r0 = lane >> 2, c0 = (lane & 3) * 2;

    for (int kt = 0; kt < 10; kt++) {
        __syncthreads();
        // ---- load K (tile 2), V (tile 3) ----
#pragma unroll
        for (int t = 0; t < 5; t++) {
            int i = tid + t * 256;
            int tile = i / 640;           // 0=K,1=V
            int rr = (i % 640) / 10, seg = i % 10;
            int row = kt * 64 + rr;
            int sz = (row < S_) ? 16 : 0;
            if (row >= S_) row = S_ - 1;
            const __half* sp = (tile ? v16 : k16) + off + (size_t)row * HD_ + seg * 8;
            cp16(sb + (2 + tile) * ATT_TILE + rr * SVB + seg * 16, sp, sz);
        }
        CP_COMMIT();
        CP_WAIT0();
        __syncthreads();

        // ---- QK^T: warp tile 16(M) x 32(N), k=80 ----
        float sacc[4][4];
#pragma unroll
        for (int ni = 0; ni < 4; ni++)
#pragma unroll
            for (int c = 0; c < 4; c++) sacc[ni][c] = 0.f;

#pragma unroll
        for (int k16i = 0; k16i < 5; k16i++) {
            uint32_t qh[4], ql[4], bf[4][2];
            uint32_t abase = sb + (wm * 16 + (lane & 15)) * SVB + (lane >> 4) * 16 + k16i * 32;
            ldx4(qh, abase);
            ldx4(ql, abase + ATT_TILE);
            uint32_t bbase = sb + 2 * ATT_TILE
                           + (wn * 32 + ((lane >> 4) << 3) + (lane & 7)) * SVB
                           + ((lane >> 3) & 1) * 16 + k16i * 32;
#pragma unroll
            for (int nt = 0; nt < 2; nt++) {
                uint32_t r[4];
                ldx4(r, bbase + nt * 16 * SVB);
                bf[nt * 2][0] = r[0]; bf[nt * 2][1] = r[1];
                bf[nt * 2 + 1][0] = r[2]; bf[nt * 2 + 1][1] = r[3];
            }
#pragma unroll
            for (int ni = 0; ni < 4; ni++) {
                hmma16(sacc[ni], qh, bf[ni]);
                hmma16(sacc[ni], ql, bf[ni]);
            }
        }

        // ---- mask + row max ----
        float mloc[2] = {-1e30f, -1e30f};
#pragma unroll
        for (int ni = 0; ni < 4; ni++)
#pragma unroll
            for (int h8 = 0; h8 < 2; h8++)
#pragma unroll
                for (int j = 0; j < 2; j++) {
                    int key = kt * 64 + wn * 32 + ni * 8 + c0 + j;
                    float sv = (key < S_) ? sacc[ni][h8 * 2 + j] : -1e30f;
                    sacc[ni][h8 * 2 + j] = sv;
                    mloc[h8] = fmaxf(mloc[h8], sv);
                }
#pragma unroll
        for (int h8 = 0; h8 < 2; h8++) {
            mloc[h8] = fmaxf(mloc[h8], __shfl_xor_sync(0xffffffffu, mloc[h8], 1));
            mloc[h8] = fmaxf(mloc[h8], __shfl_xor_sync(0xffffffffu, mloc[h8], 2));
        }
        if ((lane & 3) == 0) {
#pragma unroll
            for (int h8 = 0; h8 < 2; h8++)
                redm[(wm * 16 + r0 + h8 * 8) * 2 + wn] = mloc[h8];
        }
        __syncthreads();
        if (wn == 0 && lane < 16) {
            int row = wm * 16 + lane;
            float mn = fmaxf(fmaxf(redm[row * 2], redm[row * 2 + 1]), m_s[row]);
            al_s[row] = __expf(m_s[row] - mn);
            m_s[row] = mn;
        }
        __syncthreads();

        // ---- exp + row sum + rescale out ----
        float mn4[2], a4[2];
#pragma unroll
        for (int h8 = 0; h8 < 2; h8++) {
            int row = wm * 16 + r0 + h8 * 8;
            mn4[h8] = m_s[row];
            a4[h8] = al_s[row];
        }
        float sl[2] = {0.f, 0.f};
#pragma unroll
        for (int ni = 0; ni < 4; ni++)
#pragma unroll
            for (int h8 = 0; h8 < 2; h8++)
#pragma unroll
                for (int j = 0; j < 2; j++) {
                    float e = __expf(sacc[ni][h8 * 2 + j] - mn4[h8]);
                    sacc[ni][h8 * 2 + j] = e;
                    sl[h8] += e;
                }
#pragma unroll
        for (int h8 = 0; h8 < 2; h8++) {
            sl[h8] += __shfl_xor_sync(0xffffffffu, sl[h8], 1);
            sl[h8] += __shfl_xor_sync(0xffffffffu, sl[h8], 2);
        }
        if ((lane & 3) == 0) {
#pragma unroll
            for (int h8 = 0; h8 < 2; h8++)
                reds[(wm * 16 + r0 + h8 * 8) * 2 + wn] = sl[h8];
        }
#pragma unroll
        for (int ni = 0; ni < 10; ni++)
#pragma unroll
            for (int h8 = 0; h8 < 2; h8++) {
                out[ni][h8 * 2]     *= a4[h8];
                out[ni][h8 * 2 + 1] *= a4[h8];
            }
        __syncthreads();
        if (wn == 0 && lane < 16) {
            int row = wm * 16 + lane;
            l_s[row] = l_s[row] * al_s[row] + reds[row * 2] + reds[row * 2 + 1];
        }

        // ---- PV: P hi/lo fragments from sacc; warp k-slice = its 32 keys ----
#pragma unroll
        for (int kk = 0; kk < 2; kk++) {
            uint32_t pa_h[4], pa_l[4];
            int tni = kk * 2;
            split2h(sacc[tni][0], sacc[tni][1], pa_h[0], pa_l[0]);
            split2h(sacc[tni][2], sacc[tni][3], pa_h[1], pa_l[1]);
            split2h(sacc[tni + 1][0], sacc[tni + 1][1], pa_h[2], pa_l[2]);
            split2h(sacc[tni + 1][2], sacc[tni + 1][3], pa_h[3], pa_l[3]);

            uint32_t vbase = sb + 3 * ATT_TILE
                           + (wn * 32 + kk * 16 + (lane & 15)) * SVB + (lane >> 4) * 16;
#pragma unroll
            for (int nt = 0; nt < 5; nt++) {
                uint32_t rh[4];
                ldx4t(rh, vbase + nt * 32);
                uint32_t vb0[2] = {rh[0], rh[1]}, vb1[2] = {rh[2], rh[3]};
                hmma16(out[nt * 2], pa_h, vb0);
                hmma16(out[nt * 2], pa_l, vb0);
                hmma16(out[nt * 2 + 1], pa_h, vb1);
                hmma16(out[nt * 2 + 1], pa_l, vb1);
            }
        }
    }

    // ---- cross-warp (wn) reduction + normalize + write ----
    __syncthreads();
    float* stage = (float*)smem;   // reuse Q tiles (22528 B >= 64*84*4)
    if (wn == 1) {
#pragma unroll
        for (int ni = 0; ni < 10; ni++)
#pragma unroll
            for (int h8 = 0; h8 < 2; h8++) {
                int row = wm * 16 + r0 + h8 * 8;
                int col = ni * 8 + c0;
                stage[row * 84 + col] = out[ni][h8 * 2];
                stage[row * 84 + col + 1] = out[ni][h8 * 2 + 1];
            }
    }
    __syncthreads();
    if (wn == 0) {
#pragma unroll
        for (int h8 = 0; h8 < 2; h8++) {
            int row = wm * 16 + r0 + h8 * 8;
            int srow = q0 + row;
            if (srow >= S_) continue;
            float rl = 1.f / l_s[row];
#pragma unroll
            for (int ni = 0; ni < 10; ni++) {
                int col = ni * 8 + c0;
                float vx = (out[ni][h8 * 2] + stage[row * 84 + col]) * rl;
                float vy = (out[ni][h8 * 2 + 1] + stage[row * 84 + col + 1]) * rl;
                uint32_t hi2, lo2;
                split2h(vx, vy, hi2, lo2);
                size_t oidx = ((size_t)b * S_ + srow) * D_ + h * HD_ + col;
                *(uint32_t*)&at_hi[oidx] = hi2;
                *(uint32_t*)&at_lo[oidx] = lo2;
            }
        }
    }
}

// ----------------------------------------------------------------
extern "C" void kernel_launch(void* const* d_in, const int* in_sizes, int n_in,
                              void* d_out, int out_size)
{
    const float* hs = (const float*)d_in[0];
    const float* fc = (const float*)d_in[1];
    const float* fs = (const float*)d_in[2];
    const float* Wq = (const float*)d_in[3];
    const float* bq = (const float*)d_in[4];
    const float* Wk = (const float*)d_in[5];
    const float* bk = (const float*)d_in[6];
    const float* Wv = (const float*)d_in[7];
    const float* bv = (const float*)d_in[8];
    const float* Wo = (const float*)d_in[9];
    const float* bo = (const float*)d_in[10];
    float* out = (float*)d_out;

    __half *hshi, *hslo, *w16, *athi, *atlo, *qhi, *qlo, *k16, *v16;
    cudaGetSymbolAddress((void**)&hshi, g_hs_hi);
    cudaGetSymbolAddress((void**)&hslo, g_hs_lo);
    cudaGetSymbolAddress((void**)&w16, g_w16);
    cudaGetSymbolAddress((void**)&athi, g_at_hi);
    cudaGetSymbolAddress((void**)&atlo, g_at_lo);
    cudaGetSymbolAddress((void**)&qhi, g_q16hi);
    cudaGetSymbolAddress((void**)&qlo, g_q16lo);
    cudaGetSymbolAddress((void**)&k16, g_k16);
    cudaGetSymbolAddress((void**)&v16, g_v16);

    {
        int n = M_ * K_;
        split_h_kernel<<<(n + 255) / 256, 256>>>(hs, hshi, hslo, n);
        int nw4 = 4 * K_ * N_;
        w2h_kernel<<<(nw4 + 255) / 256, 256>>>(Wq, Wk, Wv, Wo, w16);
    }

    cudaFuncSetAttribute(gemm_hmma<0>, cudaFuncAttributeMaxDynamicSharedMemorySize,
                         GEMM_SMEM);
    cudaFuncSetAttribute(gemm_hmma<1>, cudaFuncAttributeMaxDynamicSharedMemorySize,
                         GEMM_SMEM);
    size_t wsz = (size_t)K_ * N_;

    gemm_hmma<1><<<dim3(30, (M_ + 127) / 128), 256, GEMM_SMEM>>>(
        hshi, hslo, w16, bq, bk, bv,
        nullptr, qhi, qlo, k16, v16, fc, fs, M_);

    cudaFuncSetAttribute(attn_hmma, cudaFuncAttributeMaxDynamicSharedMemorySize,
                         ATT_SMEM);
    attn_hmma<<<dim3(10, H_, B_), 256, ATT_SMEM>>>(qhi, qlo, k16, v16, athi, atlo);

    gemm_hmma<0><<<dim3(10, (M_ + 127) / 128), 256, GEMM_SMEM>>>(
        athi, atlo, w16 + 3 * wsz, bo, bo, bo,
        out, nullptr, nullptr, nullptr, nullptr, fc, fs, M_);
}

// round 9
// speedup vs baseline: 6.4899x; 1.3690x over previous
#include <cuda_runtime.h>
#include <cuda_bf16.h>
#include <cuda_fp16.h>
#include <math.h>
#include <stdint.h>

#define B_    16
#define S_    577
#define D_    1280
#define H_    16
#define HD_   80
#define HALF_ 40
#define M_    (B_*S_)   // 9232
#define K_    1280
#define N_    1280

// ---------------------------------------------------------------- scratch
__device__ __align__(16) __half g_hs16[M_*K_];
__device__ __align__(16) __half g_w16[4*K_*N_];
__device__ __align__(16) __half g_at16[M_*K_];
__device__ __align__(16) __half g_q16hi[B_*H_*S_*HD_];
__device__ __align__(16) __half g_q16lo[B_*H_*S_*HD_];
__device__ __align__(16) __half g_k16[B_*H_*S_*HD_];
__device__ __align__(16) __half g_v16[B_*H_*S_*HD_];

// ---------------------------------------------------------------- helpers
__device__ __forceinline__ uint32_t smem_u32(const void* p) {
    uint32_t a;
    asm("{ .reg .u64 t; cvta.to.shared.u64 t, %1; cvt.u32.u64 %0, t; }"
        : "=r"(a) : "l"(p));
    return a;
}
__device__ __forceinline__ void cp16(uint32_t dst, const void* src, int sz) {
    asm volatile("cp.async.cg.shared.global [%0], [%1], 16, %2;"
                 :: "r"(dst), "l"(src), "r"(sz) : "memory");
}
#define CP_COMMIT() asm volatile("cp.async.commit_group;" ::: "memory")
#define CP_WAIT0()  asm volatile("cp.async.wait_group 0;" ::: "memory")

__device__ __forceinline__ void ldx4(uint32_t* r, uint32_t addr) {
    asm volatile("ldmatrix.sync.aligned.m8n8.x4.shared.b16 {%0,%1,%2,%3}, [%4];"
                 : "=r"(r[0]), "=r"(r[1]), "=r"(r[2]), "=r"(r[3]) : "r"(addr));
}
__device__ __forceinline__ void ldx4t(uint32_t* r, uint32_t addr) {
    asm volatile("ldmatrix.sync.aligned.m8n8.x4.trans.shared.b16 {%0,%1,%2,%3}, [%4];"
                 : "=r"(r[0]), "=r"(r[1]), "=r"(r[2]), "=r"(r[3]) : "r"(addr));
}
__device__ __forceinline__ void hmma16(float* d, const uint32_t* a, const uint32_t* b) {
    asm volatile(
        "mma.sync.aligned.m16n8k16.row.col.f32.f16.f16.f32 "
        "{%0,%1,%2,%3}, {%4,%5,%6,%7}, {%8,%9}, {%0,%1,%2,%3};"
        : "+f"(d[0]), "+f"(d[1]), "+f"(d[2]), "+f"(d[3])
        : "r"(a[0]), "r"(a[1]), "r"(a[2]), "r"(a[3]), "r"(b[0]), "r"(b[1]));
}
__device__ __forceinline__ void split2h(float x, float y, uint32_t& hi, uint32_t& lo) {
    __half2 h = __floats2half2_rn(x, y);
    float hx = __half2float(h.x), hy = __half2float(h.y);
    __half2 l = __floats2half2_rn(x - hx, y - hy);
    hi = *(uint32_t*)&h; lo = *(uint32_t*)&l;
}

// ---------------------------------------------------------------- fp32 -> fp16 converts
__global__ __launch_bounds__(256)
void h_conv_kernel(const float* __restrict__ x, __half* __restrict__ y, int n)
{
    int i = blockIdx.x * blockDim.x + threadIdx.x;
    if (i >= n) return;
    y[i] = __float2half_rn(x[i]);
}

__global__ __launch_bounds__(256)
void w2h_kernel(const float* __restrict__ w0, const float* __restrict__ w1,
                const float* __restrict__ w2, const float* __restrict__ w3,
                __half* __restrict__ dst)
{
    const int nw = K_ * N_;
    int i = blockIdx.x * blockDim.x + threadIdx.x;
    if (i >= 4 * nw) return;
    int mat = i / nw, off = i - mat * nw;
    const float* src = (mat == 0) ? w0 : (mat == 1) ? w1 : (mat == 2) ? w2 : w3;
    dst[i] = __float2half_rn(src[off]);
}

// ---------------------------------------------------------------- fp16 HMMA GEMM (single pass)
#define SPADB 80
#define TILEB (128*SPADB)
#define STAGEB (2*TILEB)          // A, B = 20480
#define GEMM_SMEM (3*STAGEB)      // 3 stages = 61440
#define NIT (K_/32)

template<int MODE>
__global__ __launch_bounds__(256, 2)
void gemm_hmma(const __half* __restrict__ Ah, const __half* __restrict__ Bh,
               const float* __restrict__ bq, const float* __restrict__ bk,
               const float* __restrict__ bv,
               float* __restrict__ Cf,
               __half* __restrict__ qhi, __half* __restrict__ qlo,
               __half* __restrict__ k16, __half* __restrict__ v16,
               const float* __restrict__ fc, const float* __restrict__ fs,
               int M)
{
    extern __shared__ __align__(16) char smem[];
    const int tid = threadIdx.x, wid = tid >> 5, lane = tid & 31;
    const int bn = blockIdx.x, bm = blockIdx.y;
    const int wm = wid >> 2, wn = wid & 3;
    const int row0A = bm * 128, row0B = bn * 128;
    const uint32_t sbase = smem_u32(smem);

    float acc[4][4][4];
#pragma unroll
    for (int i = 0; i < 4; i++)
#pragma unroll
        for (int j = 0; j < 4; j++)
#pragma unroll
            for (int c = 0; c < 4; c++) acc[i][j][c] = 0.f;

    // 1024 cp16 units per stage = 4 per thread
    auto load_stage = [&](int st, int k0) {
        uint32_t sdst = sbase + st * STAGEB;
#pragma unroll
        for (int t = 0; t < 4; t++) {
            int idx = tid + t * 256;          // 0..1023
            int tile = idx >> 9;              // 0=A,1=B
            int w = idx & 511;
            int r = w >> 2, seg = w & 3;
            uint32_t d = sdst + tile * TILEB + r * SPADB + seg * 16;
            const __half* sp;
            int sz = 16;
            if (tile == 0) {
                int row = row0A + r;
                if (row >= M) { row = M - 1; sz = 0; }
                sp = Ah + (size_t)row * K_ + k0 + seg * 8;
            } else {
                int row = row0B + r;
                sp = Bh + (size_t)row * K_ + k0 + seg * 8;
            }
            cp16(d, sp, sz);
        }
        CP_COMMIT();
    };

    const uint32_t a_lane = (uint32_t)((wm * 64 + (lane & 15)) * SPADB + (lane >> 4) * 16);
    const uint32_t b_lane = (uint32_t)((wn * 32 + ((lane >> 4) << 3) + (lane & 7)) * SPADB
                                       + ((lane >> 3) & 1) * 16);

    load_stage(0, 0);
    load_stage(1, 32);

    for (int it = 0; it < NIT; it++) {
        int cur = it % 3;
        if (it + 2 < NIT) load_stage((it + 2) % 3, (it + 2) * 32);
        if (it + 2 < NIT)      { asm volatile("cp.async.wait_group 2;" ::: "memory"); }
        else if (it + 1 < NIT) { asm volatile("cp.async.wait_group 1;" ::: "memory"); }
        else                   { CP_WAIT0(); }
        __syncthreads();

        uint32_t scur = sbase + cur * STAGEB;
#pragma unroll
        for (int kk = 0; kk < 2; kk++) {
            uint32_t ab = scur + a_lane + kk * 32;
            uint32_t bb = scur + TILEB + b_lane + kk * 32;

            uint32_t af[4][4], bf[4][2];
#pragma unroll
            for (int mi = 0; mi < 4; mi++) ldx4(af[mi], ab + mi * 16 * SPADB);
#pragma unroll
            for (int np = 0; np < 2; np++) {
                uint32_t r[4];
                ldx4(r, bb + np * 16 * SPADB);
                bf[np * 2][0] = r[0]; bf[np * 2][1] = r[1];
                bf[np * 2 + 1][0] = r[2]; bf[np * 2 + 1][1] = r[3];
            }
#pragma unroll
            for (int mi = 0; mi < 4; mi++)
#pragma unroll
                for (int ni = 0; ni < 4; ni++) hmma16(acc[mi][ni], af[mi], bf[ni]);
        }
        __syncthreads();
    }

    // ---- epilogue ----
    const int mrow = (lane >> 2);
    const int ncol = (lane & 3) * 2;
    const float rscale = 0.11180339887498949f;  // 1/sqrt(80)

    int mat = 0;
    const float* bias = bq;
    if (MODE == 1) {
        mat = bn / 10;
        bias = (mat == 0) ? bq : (mat == 1) ? bk : bv;
    }
    const int nbase = (MODE == 1) ? (bn % 10) * 128 : bn * 128;

#pragma unroll
    for (int mi = 0; mi < 4; mi++) {
#pragma unroll
        for (int h2 = 0; h2 < 2; h2++) {
            int m = row0A + wm * 64 + mi * 16 + mrow + h2 * 8;
            if (m >= M) continue;
            int bb2 = m / S_, ss = m - bb2 * S_;
#pragma unroll
            for (int ni = 0; ni < 4; ni++) {
                int n0 = nbase + wn * 32 + ni * 8 + ncol;
                float vx = acc[mi][ni][h2 * 2] + bias[n0];
                float vy = acc[mi][ni][h2 * 2 + 1] + bias[n0 + 1];
                if (MODE == 0) {
                    float2 v = make_float2(vx, vy);
                    *(float2*)&Cf[(size_t)m * N_ + n0] = v;
                } else {
                    int h = n0 / HD_, d = n0 - h * HD_;
                    size_t idx = ((size_t)(bb2 * H_ + h) * S_ + ss) * HD_ + d;
                    if (mat == 0) {            // q: rope + scale + hi/lo split
                        int j = d >> 1;
                        float c = fc[ss * HALF_ + j], sn = fs[ss * HALF_ + j];
                        float rx = (vx * c - vy * sn) * rscale;
                        float ry = (vx * sn + vy * c) * rscale;
                        uint32_t hi2, lo2;
                        split2h(rx, ry, hi2, lo2);
                        *(uint32_t*)&qhi[idx] = hi2;
                        *(uint32_t*)&qlo[idx] = lo2;
                    } else if (mat == 1) {     // k: rope, single fp16
                        int j = d >> 1;
                        float c = fc[ss * HALF_ + j], sn = fs[ss * HALF_ + j];
                        float rx = vx * c - vy * sn;
                        float ry = vx * sn + vy * c;
                        __half2 hv = __floats2half2_rn(rx, ry);
                        *(__half2*)&k16[idx] = hv;
                    } else {                   // v: single fp16
                        __half2 hv = __floats2half2_rn(vx, vy);
                        *(__half2*)&v16[idx] = hv;
                    }
                }
            }
        }
    }
}

// ---------------------------------------------------------------- fp16 HMMA flash attention
// 256 threads = 8 warps: wm in 0..3 (16 q-rows each), wn in 0..1 (32-key split).
// QK = Qhi*K + Qlo*K (2 passes); PV = Phi*V + Plo*V (P split in-register).
#define SVB 176                   // 80 fp16 = 160B + 16 pad
#define ATT_TILE (64*SVB)         // 11264
#define ATT_SMEM (4*ATT_TILE + 64*4*3 + 128*4*2)

__global__ __launch_bounds__(256, 2)
void attn_hmma(const __half* __restrict__ qhi, const __half* __restrict__ qlo,
               const __half* __restrict__ k16, const __half* __restrict__ v16,
               __half* __restrict__ at16)
{
    extern __shared__ __align__(16) char smem[];
    const uint32_t sb = smem_u32(smem);
    float* m_s  = (float*)(smem + 4 * ATT_TILE);
    float* l_s  = m_s + 64;
    float* al_s = l_s + 64;
    float* redm = al_s + 64;   // [64][2]
    float* reds = redm + 128;  // [64][2]

    const int tid = threadIdx.x, wid = tid >> 5, lane = tid & 31;
    const int wm = wid >> 1, wn = wid & 1;
    const int qt = blockIdx.x, h = blockIdx.y, b = blockIdx.z;
    const int bh = b * H_ + h;
    const size_t off = (size_t)bh * S_ * HD_;
    const int q0 = qt * 64;

    // ---- load Q hi/lo (tiles 0,1) ----
#pragma unroll
    for (int t = 0; t < 5; t++) {
        int i = tid + t * 256;            // 0..1279
        int tile = i / 640;               // 0=Qhi,1=Qlo
        int rr = (i % 640) / 10, seg = i % 10;
        int row = q0 + rr;
        int sz = (row < S_) ? 16 : 0;
        if (row >= S_) row = S_ - 1;
        const __half* sp = (tile ? qlo : qhi) + off + (size_t)row * HD_ + seg * 8;
        cp16(sb + tile * ATT_TILE + rr * SVB + seg * 16, sp, sz);
    }
    CP_COMMIT();

    if (tid < 64) { m_s[tid] = -1e30f; l_s[tid] = 0.f; }

    float out[10][4];
#pragma unroll
    for (int ni = 0; ni < 10; ni++)
#pragma unroll
        for (int c = 0; c < 4; c++) out[ni][c] = 0.f;

    const int r0 = lane >> 2, c0 = (lane & 3) * 2;

    for (int kt = 0; kt < 10; kt++) {
        __syncthreads();
        // ---- load K (tile 2), V (tile 3) ----
#pragma unroll
        for (int t = 0; t < 5; t++) {
            int i = tid + t * 256;
            int tile = i / 640;           // 0=K,1=V
            int rr = (i % 640) / 10, seg = i % 10;
            int row = kt * 64 + rr;
            int sz = (row < S_) ? 16 : 0;
            if (row >= S_) row = S_ - 1;
            const __half* sp = (tile ? v16 : k16) + off + (size_t)row * HD_ + seg * 8;
            cp16(sb + (2 + tile) * ATT_TILE + rr * SVB + seg * 16, sp, sz);
        }
        CP_COMMIT();
        CP_WAIT0();
        __syncthreads();

        // ---- QK^T: warp tile 16(M) x 32(N), k=80 ----
        float sacc[4][4];
#pragma unroll
        for (int ni = 0; ni < 4; ni++)
#pragma unroll
            for (int c = 0; c < 4; c++) sacc[ni][c] = 0.f;

#pragma unroll
        for (int k16i = 0; k16i < 5; k16i++) {
            uint32_t qh[4], ql[4], bf[4][2];
            uint32_t abase = sb + (wm * 16 + (lane & 15)) * SVB + (lane >> 4) * 16 + k16i * 32;
            ldx4(qh, abase);
            ldx4(ql, abase + ATT_TILE);
            uint32_t bbase = sb + 2 * ATT_TILE
                           + (wn * 32 + ((lane >> 4) << 3) + (lane & 7)) * SVB
                           + ((lane >> 3) & 1) * 16 + k16i * 32;
#pragma unroll
            for (int nt = 0; nt < 2; nt++) {
                uint32_t r[4];
                ldx4(r, bbase + nt * 16 * SVB);
                bf[nt * 2][0] = r[0]; bf[nt * 2][1] = r[1];
                bf[nt * 2 + 1][0] = r[2]; bf[nt * 2 + 1][1] = r[3];
            }
#pragma unroll
            for (int ni = 0; ni < 4; ni++) {
                hmma16(sacc[ni], qh, bf[ni]);
                hmma16(sacc[ni], ql, bf[ni]);
            }
        }

        // ---- mask + row max ----
        float mloc[2] = {-1e30f, -1e30f};
#pragma unroll
        for (int ni = 0; ni < 4; ni++)
#pragma unroll
            for (int h8 = 0; h8 < 2; h8++)
#pragma unroll
                for (int j = 0; j < 2; j++) {
                    int key = kt * 64 + wn * 32 + ni * 8 + c0 + j;
                    float sv = (key < S_) ? sacc[ni][h8 * 2 + j] : -1e30f;
                    sacc[ni][h8 * 2 + j] = sv;
                    mloc[h8] = fmaxf(mloc[h8], sv);
                }
#pragma unroll
        for (int h8 = 0; h8 < 2; h8++) {
            mloc[h8] = fmaxf(mloc[h8], __shfl_xor_sync(0xffffffffu, mloc[h8], 1));
            mloc[h8] = fmaxf(mloc[h8], __shfl_xor_sync(0xffffffffu, mloc[h8], 2));
        }
        if ((lane & 3) == 0) {
#pragma unroll
            for (int h8 = 0; h8 < 2; h8++)
                redm[(wm * 16 + r0 + h8 * 8) * 2 + wn] = mloc[h8];
        }
        __syncthreads();
        if (wn == 0 && lane < 16) {
            int row = wm * 16 + lane;
            float mn = fmaxf(fmaxf(redm[row * 2], redm[row * 2 + 1]), m_s[row]);
            al_s[row] = __expf(m_s[row] - mn);
            m_s[row] = mn;
        }
        __syncthreads();

        // ---- exp + row sum + rescale out ----
        float mn4[2], a4[2];
#pragma unroll
        for (int h8 = 0; h8 < 2; h8++) {
            int row = wm * 16 + r0 + h8 * 8;
            mn4[h8] = m_s[row];
            a4[h8] = al_s[row];
        }
        float sl[2] = {0.f, 0.f};
#pragma unroll
        for (int ni = 0; ni < 4; ni++)
#pragma unroll
            for (int h8 = 0; h8 < 2; h8++)
#pragma unroll
                for (int j = 0; j < 2; j++) {
                    float e = __expf(sacc[ni][h8 * 2 + j] - mn4[h8]);
                    sacc[ni][h8 * 2 + j] = e;
                    sl[h8] += e;
                }
#pragma unroll
        for (int h8 = 0; h8 < 2; h8++) {
            sl[h8] += __shfl_xor_sync(0xffffffffu, sl[h8], 1);
            sl[h8] += __shfl_xor_sync(0xffffffffu, sl[h8], 2);
        }
        if ((lane & 3) == 0) {
#pragma unroll
            for (int h8 = 0; h8 < 2; h8++)
                reds[(wm * 16 + r0 + h8 * 8) * 2 + wn] = sl[h8];
        }
#pragma unroll
        for (int ni = 0; ni < 10; ni++)
#pragma unroll
            for (int h8 = 0; h8 < 2; h8++) {
                out[ni][h8 * 2]     *= a4[h8];
                out[ni][h8 * 2 + 1] *= a4[h8];
            }
        __syncthreads();
        if (wn == 0 && lane < 16) {
            int row = wm * 16 + lane;
            l_s[row] = l_s[row] * al_s[row] + reds[row * 2] + reds[row * 2 + 1];
        }

        // ---- PV: P hi/lo fragments from sacc; warp k-slice = its 32 keys ----
#pragma unroll
        for (int kk = 0; kk < 2; kk++) {
            uint32_t pa_h[4], pa_l[4];
            int tni = kk * 2;
            split2h(sacc[tni][0], sacc[tni][1], pa_h[0], pa_l[0]);
            split2h(sacc[tni][2], sacc[tni][3], pa_h[1], pa_l[1]);
            split2h(sacc[tni + 1][0], sacc[tni + 1][1], pa_h[2], pa_l[2]);
            split2h(sacc[tni + 1][2], sacc[tni + 1][3], pa_h[3], pa_l[3]);

            uint32_t vbase = sb + 3 * ATT_TILE
                           + (wn * 32 + kk * 16 + (lane & 15)) * SVB + (lane >> 4) * 16;
#pragma unroll
            for (int nt = 0; nt < 5; nt++) {
                uint32_t rh[4];
                ldx4t(rh, vbase + nt * 32);
                uint32_t vb0[2] = {rh[0], rh[1]}, vb1[2] = {rh[2], rh[3]};
                hmma16(out[nt * 2], pa_h, vb0);
                hmma16(out[nt * 2], pa_l, vb0);
                hmma16(out[nt * 2 + 1], pa_h, vb1);
                hmma16(out[nt * 2 + 1], pa_l, vb1);
            }
        }
    }

    // ---- cross-warp (wn) reduction + normalize + write ----
    __syncthreads();
    float* stage = (float*)smem;   // reuse Q tiles (22528 B >= 64*84*4)
    if (wn == 1) {
#pragma unroll
        for (int ni = 0; ni < 10; ni++)
#pragma unroll
            for (int h8 = 0; h8 < 2; h8++) {
                int row = wm * 16 + r0 + h8 * 8;
                int col = ni * 8 + c0;
                stage[row * 84 + col] = out[ni][h8 * 2];
                stage[row * 84 + col + 1] = out[ni][h8 * 2 + 1];
            }
    }
    __syncthreads();
    if (wn == 0) {
#pragma unroll
        for (int h8 = 0; h8 < 2; h8++) {
            int row = wm * 16 + r0 + h8 * 8;
            int srow = q0 + row;
            if (srow >= S_) continue;
            float rl = 1.f / l_s[row];
#pragma unroll
            for (int ni = 0; ni < 10; ni++) {
                int col = ni * 8 + c0;
                float vx = (out[ni][h8 * 2] + stage[row * 84 + col]) * rl;
                float vy = (out[ni][h8 * 2 + 1] + stage[row * 84 + col + 1]) * rl;
                __half2 hv = __floats2half2_rn(vx, vy);
                size_t oidx = ((size_t)b * S_ + srow) * D_ + h * HD_ + col;
                *(__half2*)&at16[oidx] = hv;
            }
        }
    }
}

// ----------------------------------------------------------------
extern "C" void kernel_launch(void* const* d_in, const int* in_sizes, int n_in,
                              void* d_out, int out_size)
{
    const float* hs = (const float*)d_in[0];
    const float* fc = (const float*)d_in[1];
    const float* fs = (const float*)d_in[2];
    const float* Wq = (const float*)d_in[3];
    const float* bq = (const float*)d_in[4];
    const float* Wk = (const float*)d_in[5];
    const float* bk = (const float*)d_in[6];
    const float* Wv = (const float*)d_in[7];
    const float* bv = (const float*)d_in[8];
    const float* Wo = (const float*)d_in[9];
    const float* bo = (const float*)d_in[10];
    float* out = (float*)d_out;

    __half *hs16, *w16, *at16, *qhi, *qlo, *k16, *v16;
    cudaGetSymbolAddress((void**)&hs16, g_hs16);
    cudaGetSymbolAddress((void**)&w16, g_w16);
    cudaGetSymbolAddress((void**)&at16, g_at16);
    cudaGetSymbolAddress((void**)&qhi, g_q16hi);
    cudaGetSymbolAddress((void**)&qlo, g_q16lo);
    cudaGetSymbolAddress((void**)&k16, g_k16);
    cudaGetSymbolAddress((void**)&v16, g_v16);

    {
        int n = M_ * K_;
        h_conv_kernel<<<(n + 255) / 256, 256>>>(hs, hs16, n);
        int nw4 = 4 * K_ * N_;
        w2h_kernel<<<(nw4 + 255) / 256, 256>>>(Wq, Wk, Wv, Wo, w16);
    }

    cudaFuncSetAttribute(gemm_hmma<0>, cudaFuncAttributeMaxDynamicSharedMemorySize,
                         GEMM_SMEM);
    cudaFuncSetAttribute(gemm_hmma<1>, cudaFuncAttributeMaxDynamicSharedMemorySize,
                         GEMM_SMEM);
    size_t wsz = (size_t)K_ * N_;

    gemm_hmma<1><<<dim3(30, (M_ + 127) / 128), 256, GEMM_SMEM>>>(
        hs16, w16, bq, bk, bv,
        nullptr, qhi, qlo, k16, v16, fc, fs, M_);

    cudaFuncSetAttribute(attn_hmma, cudaFuncAttributeMaxDynamicSharedMemorySize,
                         ATT_SMEM);
    attn_hmma<<<dim3(10, H_, B_), 256, ATT_SMEM>>>(qhi, qlo, k16, v16, at16);

    gemm_hmma<0><<<dim3(10, (M_ + 127) / 128), 256, GEMM_SMEM>>>(
        at16, w16 + 3 * wsz, bo, bo, bo,
        out, nullptr, nullptr, nullptr, nullptr, fc, fs, M_);
}

// round 10
// speedup vs baseline: 7.0147x; 1.0809x over previous
#include <cuda_runtime.h>
#include <cuda_bf16.h>
#include <cuda_fp16.h>
#include <math.h>
#include <stdint.h>

#define B_    16
#define S_    577
#define D_    1280
#define H_    16
#define HD_   80
#define HALF_ 40
#define M_    (B_*S_)   // 9232
#define K_    1280
#define N_    1280

// ---------------------------------------------------------------- scratch
__device__ __align__(16) __half g_hs16[M_*K_];
__device__ __align__(16) __half g_w16[4*K_*N_];
__device__ __align__(16) __half g_at16[M_*K_];
__device__ __align__(16) __half g_q16hi[B_*H_*S_*HD_];
__device__ __align__(16) __half g_q16lo[B_*H_*S_*HD_];
__device__ __align__(16) __half g_k16[B_*H_*S_*HD_];
__device__ __align__(16) __half g_v16[B_*H_*S_*HD_];

// ---------------------------------------------------------------- helpers
__device__ __forceinline__ uint32_t smem_u32(const void* p) {
    uint32_t a;
    asm("{ .reg .u64 t; cvta.to.shared.u64 t, %1; cvt.u32.u64 %0, t; }"
        : "=r"(a) : "l"(p));
    return a;
}
__device__ __forceinline__ void cp16(uint32_t dst, const void* src, int sz) {
    asm volatile("cp.async.cg.shared.global [%0], [%1], 16, %2;"
                 :: "r"(dst), "l"(src), "r"(sz) : "memory");
}
#define CP_COMMIT() asm volatile("cp.async.commit_group;" ::: "memory")
#define CP_WAIT0()  asm volatile("cp.async.wait_group 0;" ::: "memory")
#define CP_WAIT1()  asm volatile("cp.async.wait_group 1;" ::: "memory")

__device__ __forceinline__ void ldx4(uint32_t* r, uint32_t addr) {
    asm volatile("ldmatrix.sync.aligned.m8n8.x4.shared.b16 {%0,%1,%2,%3}, [%4];"
                 : "=r"(r[0]), "=r"(r[1]), "=r"(r[2]), "=r"(r[3]) : "r"(addr));
}
__device__ __forceinline__ void ldx4t(uint32_t* r, uint32_t addr) {
    asm volatile("ldmatrix.sync.aligned.m8n8.x4.trans.shared.b16 {%0,%1,%2,%3}, [%4];"
                 : "=r"(r[0]), "=r"(r[1]), "=r"(r[2]), "=r"(r[3]) : "r"(addr));
}
__device__ __forceinline__ void hmma16(float* d, const uint32_t* a, const uint32_t* b) {
    asm volatile(
        "mma.sync.aligned.m16n8k16.row.col.f32.f16.f16.f32 "
        "{%0,%1,%2,%3}, {%4,%5,%6,%7}, {%8,%9}, {%0,%1,%2,%3};"
        : "+f"(d[0]), "+f"(d[1]), "+f"(d[2]), "+f"(d[3])
        : "r"(a[0]), "r"(a[1]), "r"(a[2]), "r"(a[3]), "r"(b[0]), "r"(b[1]));
}
__device__ __forceinline__ void split2h(float x, float y, uint32_t& hi, uint32_t& lo) {
    __half2 h = __floats2half2_rn(x, y);
    float hx = __half2float(h.x), hy = __half2float(h.y);
    __half2 l = __floats2half2_rn(x - hx, y - hy);
    hi = *(uint32_t*)&h; lo = *(uint32_t*)&l;
}

// ---------------------------------------------------------------- fp32 -> fp16 converts
__global__ __launch_bounds__(256)
void h_conv_kernel(const float* __restrict__ x, __half* __restrict__ y, int n)
{
    int i = blockIdx.x * blockDim.x + threadIdx.x;
    if (i >= n) return;
    y[i] = __float2half_rn(x[i]);
}

__global__ __launch_bounds__(256)
void w2h_kernel(const float* __restrict__ w0, const float* __restrict__ w1,
                const float* __restrict__ w2, const float* __restrict__ w3,
                __half* __restrict__ dst)
{
    const int nw = K_ * N_;
    int i = blockIdx.x * blockDim.x + threadIdx.x;
    if (i >= 4 * nw) return;
    int mat = i / nw, off = i - mat * nw;
    const float* src = (mat == 0) ? w0 : (mat == 1) ? w1 : (mat == 2) ? w2 : w3;
    dst[i] = __float2half_rn(src[off]);
}

// ---------------------------------------------------------------- fp16 HMMA GEMM (single pass)
#define SPADB 80
#define TILEB (128*SPADB)
#define STAGEB (2*TILEB)
#define GEMM_SMEM (3*STAGEB)
#define NIT (K_/32)

template<int MODE>
__global__ __launch_bounds__(256, 2)
void gemm_hmma(const __half* __restrict__ Ah, const __half* __restrict__ Bh,
               const float* __restrict__ bq, const float* __restrict__ bk,
               const float* __restrict__ bv,
               float* __restrict__ Cf,
               __half* __restrict__ qhi, __half* __restrict__ qlo,
               __half* __restrict__ k16, __half* __restrict__ v16,
               const float* __restrict__ fc, const float* __restrict__ fs,
               int M)
{
    extern __shared__ __align__(16) char smem[];
    const int tid = threadIdx.x, wid = tid >> 5, lane = tid & 31;
    const int bn = blockIdx.x, bm = blockIdx.y;
    const int wm = wid >> 2, wn = wid & 3;
    const int row0A = bm * 128, row0B = bn * 128;
    const uint32_t sbase = smem_u32(smem);

    float acc[4][4][4];
#pragma unroll
    for (int i = 0; i < 4; i++)
#pragma unroll
        for (int j = 0; j < 4; j++)
#pragma unroll
            for (int c = 0; c < 4; c++) acc[i][j][c] = 0.f;

    auto load_stage = [&](int st, int k0) {
        uint32_t sdst = sbase + st * STAGEB;
#pragma unroll
        for (int t = 0; t < 4; t++) {
            int idx = tid + t * 256;
            int tile = idx >> 9;
            int w = idx & 511;
            int r = w >> 2, seg = w & 3;
            uint32_t d = sdst + tile * TILEB + r * SPADB + seg * 16;
            const __half* sp;
            int sz = 16;
            if (tile == 0) {
                int row = row0A + r;
                if (row >= M) { row = M - 1; sz = 0; }
                sp = Ah + (size_t)row * K_ + k0 + seg * 8;
            } else {
                int row = row0B + r;
                sp = Bh + (size_t)row * K_ + k0 + seg * 8;
            }
            cp16(d, sp, sz);
        }
        CP_COMMIT();
    };

    const uint32_t a_lane = (uint32_t)((wm * 64 + (lane & 15)) * SPADB + (lane >> 4) * 16);
    const uint32_t b_lane = (uint32_t)((wn * 32 + ((lane >> 4) << 3) + (lane & 7)) * SPADB
                                       + ((lane >> 3) & 1) * 16);

    load_stage(0, 0);
    load_stage(1, 32);

    for (int it = 0; it < NIT; it++) {
        int cur = it % 3;
        if (it + 2 < NIT) load_stage((it + 2) % 3, (it + 2) * 32);
        if (it + 2 < NIT)      { asm volatile("cp.async.wait_group 2;" ::: "memory"); }
        else if (it + 1 < NIT) { CP_WAIT1(); }
        else                   { CP_WAIT0(); }
        __syncthreads();

        uint32_t scur = sbase + cur * STAGEB;
#pragma unroll
        for (int kk = 0; kk < 2; kk++) {
            uint32_t ab = scur + a_lane + kk * 32;
            uint32_t bb = scur + TILEB + b_lane + kk * 32;

            uint32_t af[4][4], bf[4][2];
#pragma unroll
            for (int mi = 0; mi < 4; mi++) ldx4(af[mi], ab + mi * 16 * SPADB);
#pragma unroll
            for (int np = 0; np < 2; np++) {
                uint32_t r[4];
                ldx4(r, bb + np * 16 * SPADB);
                bf[np * 2][0] = r[0]; bf[np * 2][1] = r[1];
                bf[np * 2 + 1][0] = r[2]; bf[np * 2 + 1][1] = r[3];
            }
#pragma unroll
            for (int mi = 0; mi < 4; mi++)
#pragma unroll
                for (int ni = 0; ni < 4; ni++) hmma16(acc[mi][ni], af[mi], bf[ni]);
        }
        __syncthreads();
    }

    // ---- epilogue ----
    const int mrow = (lane >> 2);
    const int ncol = (lane & 3) * 2;
    const float rscale = 0.11180339887498949f;  // 1/sqrt(80)

    int mat = 0;
    const float* bias = bq;
    if (MODE == 1) {
        mat = bn / 10;
        bias = (mat == 0) ? bq : (mat == 1) ? bk : bv;
    }
    const int nbase = (MODE == 1) ? (bn % 10) * 128 : bn * 128;

#pragma unroll
    for (int mi = 0; mi < 4; mi++) {
#pragma unroll
        for (int h2 = 0; h2 < 2; h2++) {
            int m = row0A + wm * 64 + mi * 16 + mrow + h2 * 8;
            if (m >= M) continue;
            int bb2 = m / S_, ss = m - bb2 * S_;
#pragma unroll
            for (int ni = 0; ni < 4; ni++) {
                int n0 = nbase + wn * 32 + ni * 8 + ncol;
                float vx = acc[mi][ni][h2 * 2] + bias[n0];
                float vy = acc[mi][ni][h2 * 2 + 1] + bias[n0 + 1];
                if (MODE == 0) {
                    float2 v = make_float2(vx, vy);
                    *(float2*)&Cf[(size_t)m * N_ + n0] = v;
                } else {
                    int h = n0 / HD_, d = n0 - h * HD_;
                    size_t idx = ((size_t)(bb2 * H_ + h) * S_ + ss) * HD_ + d;
                    if (mat == 0) {
                        int j = d >> 1;
                        float c = fc[ss * HALF_ + j], sn = fs[ss * HALF_ + j];
                        float rx = (vx * c - vy * sn) * rscale;
                        float ry = (vx * sn + vy * c) * rscale;
                        uint32_t hi2, lo2;
                        split2h(rx, ry, hi2, lo2);
                        *(uint32_t*)&qhi[idx] = hi2;
                        *(uint32_t*)&qlo[idx] = lo2;
                    } else if (mat == 1) {
                        int j = d >> 1;
                        float c = fc[ss * HALF_ + j], sn = fs[ss * HALF_ + j];
                        float rx = vx * c - vy * sn;
                        float ry = vx * sn + vy * c;
                        __half2 hv = __floats2half2_rn(rx, ry);
                        *(__half2*)&k16[idx] = hv;
                    } else {
                        __half2 hv = __floats2half2_rn(vx, vy);
                        *(__half2*)&v16[idx] = hv;
                    }
                }
            }
        }
    }
}

// ---------------------------------------------------------------- fp16 HMMA flash attention
// BQ=128, 8 warps; warp w owns rows w*16..w*16+15 x ALL 64 keys of each tile.
// Fully warp-local softmax (registers + quad shuffles); 1 syncthreads/iter;
// double-buffered K/V via cp.async groups.
#define ASVB 176                  // 80 fp16 = 160B + 16 pad
#define AQ_TILE (128*ASVB)        // 22528
#define AKV_TILE (64*ASVB)        // 11264
#define ATT_SMEM (2*AQ_TILE + 4*AKV_TILE)   // 90112

__global__ __launch_bounds__(256, 2)
void attn_hmma(const __half* __restrict__ qhi, const __half* __restrict__ qlo,
               const __half* __restrict__ k16, const __half* __restrict__ v16,
               __half* __restrict__ at16)
{
    extern __shared__ __align__(16) char smem[];
    const uint32_t sb = smem_u32(smem);
    const uint32_t kv0 = sb + 2 * AQ_TILE;

    const int tid = threadIdx.x, wid = tid >> 5, lane = tid & 31;
    const int qt = blockIdx.x, h = blockIdx.y, b = blockIdx.z;
    const int bh = b * H_ + h;
    const size_t off = (size_t)bh * S_ * HD_;
    const int q0 = qt * 128;

    // ---- Q hi/lo loads: 2560 cp16 units = 10/thread ----
#pragma unroll
    for (int t = 0; t < 10; t++) {
        int i = tid + t * 256;
        int tile = i / 1280;              // 0=Qhi,1=Qlo
        int rr = (i % 1280) / 10, seg = i % 10;
        int row = q0 + rr;
        int sz = (row < S_) ? 16 : 0;
        if (row >= S_) row = S_ - 1;
        const __half* sp = (tile ? qlo : qhi) + off + (size_t)row * HD_ + seg * 8;
        cp16(sb + tile * AQ_TILE + rr * ASVB + seg * 16, sp, sz);
    }
    CP_COMMIT();

    // ---- KV stage loader: 1280 units = 5/thread ----
    auto load_kv = [&](int stage, int kt) {
#pragma unroll
        for (int t = 0; t < 5; t++) {
            int i = tid + t * 256;
            int tile = i / 640;           // 0=K,1=V
            int rr = (i % 640) / 10, seg = i % 10;
            int row = kt * 64 + rr;
            int sz = (row < S_) ? 16 : 0;
            if (row >= S_) row = S_ - 1;
            const __half* sp = (tile ? v16 : k16) + off + (size_t)row * HD_ + seg * 8;
            cp16(kv0 + (stage * 2 + tile) * AKV_TILE + rr * ASVB + seg * 16, sp, sz);
        }
        CP_COMMIT();
    };
    load_kv(0, 0);
    load_kv(1, 1);
    CP_WAIT1();                 // Q + KV0 complete
    __syncthreads();

    const int r0 = lane >> 2, c0 = (lane & 3) * 2;
    float mreg[2] = {-1e30f, -1e30f};
    float lreg[2] = {0.f, 0.f};
    float out[10][4];
#pragma unroll
    for (int ni = 0; ni < 10; ni++)
#pragma unroll
        for (int c = 0; c < 4; c++) out[ni][c] = 0.f;

    for (int kt = 0; kt < 10; kt++) {
        const int cur = kt & 1;
        const uint32_t kbase = kv0 + cur * 2 * AKV_TILE;
        const uint32_t vbase0 = kbase + AKV_TILE;

        // ---- QK^T: 16 rows x 64 keys, k=80, Q hi+lo (2 passes) ----
        float sacc[8][4];
#pragma unroll
        for (int ni = 0; ni < 8; ni++)
#pragma unroll
            for (int c = 0; c < 4; c++) sacc[ni][c] = 0.f;

#pragma unroll
        for (int k16i = 0; k16i < 5; k16i++) {
            uint32_t qh[4], ql[4], bf[8][2];
            uint32_t abase = sb + (wid * 16 + (lane & 15)) * ASVB
                           + (lane >> 4) * 16 + k16i * 32;
            ldx4(qh, abase);
            ldx4(ql, abase + AQ_TILE);
#pragma unroll
            for (int nt = 0; nt < 4; nt++) {
                uint32_t r[4];
                uint32_t bb = kbase + (nt * 16 + ((lane >> 4) << 3) + (lane & 7)) * ASVB
                            + ((lane >> 3) & 1) * 16 + k16i * 32;
                ldx4(r, bb);
                bf[nt * 2][0] = r[0]; bf[nt * 2][1] = r[1];
                bf[nt * 2 + 1][0] = r[2]; bf[nt * 2 + 1][1] = r[3];
            }
#pragma unroll
            for (int ni = 0; ni < 8; ni++) {
                hmma16(sacc[ni], qh, bf[ni]);
                hmma16(sacc[ni], ql, bf[ni]);
            }
        }

        // ---- mask + warp-local row max (quad butterfly) ----
        float mloc[2] = {-1e30f, -1e30f};
#pragma unroll
        for (int ni = 0; ni < 8; ni++)
#pragma unroll
            for (int h8 = 0; h8 < 2; h8++)
#pragma unroll
                for (int j = 0; j < 2; j++) {
                    int key = kt * 64 + ni * 8 + c0 + j;
                    float sv = (key < S_) ? sacc[ni][h8 * 2 + j] : -1e30f;
                    sacc[ni][h8 * 2 + j] = sv;
                    mloc[h8] = fmaxf(mloc[h8], sv);
                }
        float alpha[2];
#pragma unroll
        for (int h8 = 0; h8 < 2; h8++) {
            mloc[h8] = fmaxf(mloc[h8], __shfl_xor_sync(0xffffffffu, mloc[h8], 1));
            mloc[h8] = fmaxf(mloc[h8], __shfl_xor_sync(0xffffffffu, mloc[h8], 2));
            float mn = fmaxf(mloc[h8], mreg[h8]);
            alpha[h8] = __expf(mreg[h8] - mn);
            mreg[h8] = mn;
        }

        // ---- exp + row sum + rescale ----
        float sl[2] = {0.f, 0.f};
#pragma unroll
        for (int ni = 0; ni < 8; ni++)
#pragma unroll
            for (int h8 = 0; h8 < 2; h8++)
#pragma unroll
                for (int j = 0; j < 2; j++) {
                    float e = __expf(sacc[ni][h8 * 2 + j] - mreg[h8]);
                    sacc[ni][h8 * 2 + j] = e;
                    sl[h8] += e;
                }
#pragma unroll
        for (int h8 = 0; h8 < 2; h8++) {
            sl[h8] += __shfl_xor_sync(0xffffffffu, sl[h8], 1);
            sl[h8] += __shfl_xor_sync(0xffffffffu, sl[h8], 2);
            lreg[h8] = lreg[h8] * alpha[h8] + sl[h8];
        }
#pragma unroll
        for (int ni = 0; ni < 10; ni++)
#pragma unroll
            for (int h8 = 0; h8 < 2; h8++) {
                out[ni][h8 * 2]     *= alpha[h8];
                out[ni][h8 * 2 + 1] *= alpha[h8];
            }

        // ---- PV over full 64-key tile: 4 k16 steps, P hi/lo ----
#pragma unroll
        for (int kk = 0; kk < 4; kk++) {
            uint32_t pa_h[4], pa_l[4];
            int tni = kk * 2;
            split2h(sacc[tni][0], sacc[tni][1], pa_h[0], pa_l[0]);
            split2h(sacc[tni][2], sacc[tni][3], pa_h[1], pa_l[1]);
            split2h(sacc[tni + 1][0], sacc[tni + 1][1], pa_h[2], pa_l[2]);
            split2h(sacc[tni + 1][2], sacc[tni + 1][3], pa_h[3], pa_l[3]);

            uint32_t vb = vbase0 + (kk * 16 + (lane & 15)) * ASVB + (lane >> 4) * 16;
#pragma unroll
            for (int nt = 0; nt < 5; nt++) {
                uint32_t rh[4];
                ldx4t(rh, vb + nt * 32);
                uint32_t vb0[2] = {rh[0], rh[1]}, vb1[2] = {rh[2], rh[3]};
                hmma16(out[nt * 2], pa_h, vb0);
                hmma16(out[nt * 2], pa_l, vb0);
                hmma16(out[nt * 2 + 1], pa_h, vb1);
                hmma16(out[nt * 2 + 1], pa_l, vb1);
            }
        }

        // ---- pipeline handoff: 1 sync per iteration ----
        __syncthreads();
        if (kt + 2 < 10) {
            load_kv(cur, kt + 2);     // reuse the buffer just consumed
            CP_WAIT1();               // ensure stage kt+1 complete
        } else if (kt + 1 < 10) {
            CP_WAIT0();
        }
    }

    // ---- normalize + write (no cross-warp reduction needed) ----
#pragma unroll
    for (int h8 = 0; h8 < 2; h8++) {
        int row = wid * 16 + r0 + h8 * 8;
        int srow = q0 + row;
        if (srow >= S_) continue;
        float rl = 1.f / lreg[h8];
#pragma unroll
        for (int ni = 0; ni < 10; ni++) {
            int col = ni * 8 + c0;
            float vx = out[ni][h8 * 2] * rl;
            float vy = out[ni][h8 * 2 + 1] * rl;
            __half2 hv = __floats2half2_rn(vx, vy);
            size_t oidx = ((size_t)b * S_ + srow) * D_ + h * HD_ + col;
            *(__half2*)&at16[oidx] = hv;
        }
    }
}

// ----------------------------------------------------------------
extern "C" void kernel_launch(void* const* d_in, const int* in_sizes, int n_in,
                              void* d_out, int out_size)
{
    const float* hs = (const float*)d_in[0];
    const float* fc = (const float*)d_in[1];
    const float* fs = (const float*)d_in[2];
    const float* Wq = (const float*)d_in[3];
    const float* bq = (const float*)d_in[4];
    const float* Wk = (const float*)d_in[5];
    const float* bk = (const float*)d_in[6];
    const float* Wv = (const float*)d_in[7];
    const float* bv = (const float*)d_in[8];
    const float* Wo = (const float*)d_in[9];
    const float* bo = (const float*)d_in[10];
    float* out = (float*)d_out;

    __half *hs16, *w16, *at16, *qhi, *qlo, *k16, *v16;
    cudaGetSymbolAddress((void**)&hs16, g_hs16);
    cudaGetSymbolAddress((void**)&w16, g_w16);
    cudaGetSymbolAddress((void**)&at16, g_at16);
    cudaGetSymbolAddress((void**)&qhi, g_q16hi);
    cudaGetSymbolAddress((void**)&qlo, g_q16lo);
    cudaGetSymbolAddress((void**)&k16, g_k16);
    cudaGetSymbolAddress((void**)&v16, g_v16);

    {
        int n = M_ * K_;
        h_conv_kernel<<<(n + 255) / 256, 256>>>(hs, hs16, n);
        int nw4 = 4 * K_ * N_;
        w2h_kernel<<<(nw4 + 255) / 256, 256>>>(Wq, Wk, Wv, Wo, w16);
    }

    cudaFuncSetAttribute(gemm_hmma<0>, cudaFuncAttributeMaxDynamicSharedMemorySize,
                         GEMM_SMEM);
    cudaFuncSetAttribute(gemm_hmma<1>, cudaFuncAttributeMaxDynamicSharedMemorySize,
                         GEMM_SMEM);
    size_t wsz = (size_t)K_ * N_;

    gemm_hmma<1><<<dim3(30, (M_ + 127) / 128), 256, GEMM_SMEM>>>(
        hs16, w16, bq, bk, bv,
        nullptr, qhi, qlo, k16, v16, fc, fs, M_);

    cudaFuncSetAttribute(attn_hmma, cudaFuncAttributeMaxDynamicSharedMemorySize,
                         ATT_SMEM);
    attn_hmma<<<dim3(5, H_, B_), 256, ATT_SMEM>>>(qhi, qlo, k16, v16, at16);

    gemm_hmma<0><<<dim3(10, (M_ + 127) / 128), 256, GEMM_SMEM>>>(
        at16, w16 + 3 * wsz, bo, bo, bo,
        out, nullptr, nullptr, nullptr, nullptr, fc, fs, M_);
}